// round 9
// baseline (speedup 1.0000x reference)
#include <cuda_runtime.h>
#include <cuda_bf16.h>
#include <math.h>
#include <stdint.h>

#define NV 4000
#define NL 8000          // 2*NV literals
#define NC 16800
#define NE 50400         // NC*3 edges
#define FM 256
#define ROUNDS 32

// ---------------------------------------------------------------------------
// PTX helpers (baseline ISA only: ldmatrix + mma.sync + cp.async, sm_80+)
// ---------------------------------------------------------------------------
__device__ __forceinline__ uint32_t smem_u32(const void* p) {
    uint32_t a;
    asm("{ .reg .u64 t; cvta.to.shared.u64 t, %1; cvt.u32.u64 %0, t; }"
        : "=r"(a) : "l"(p));
    return a;
}
__device__ __forceinline__ void ldsm_x4(uint32_t& r0, uint32_t& r1,
                                        uint32_t& r2, uint32_t& r3, uint32_t a) {
    asm volatile("ldmatrix.sync.aligned.m8n8.x4.shared.b16 {%0,%1,%2,%3}, [%4];"
                 : "=r"(r0), "=r"(r1), "=r"(r2), "=r"(r3) : "r"(a));
}
__device__ __forceinline__ void ldsm_x2(uint32_t& r0, uint32_t& r1, uint32_t a) {
    asm volatile("ldmatrix.sync.aligned.m8n8.x2.shared.b16 {%0,%1}, [%2];"
                 : "=r"(r0), "=r"(r1) : "r"(a));
}
__device__ __forceinline__ void mma_bf16(float* c, const uint32_t* a,
                                         const uint32_t* b) {
    asm volatile(
        "mma.sync.aligned.m16n8k16.row.col.f32.bf16.bf16.f32 "
        "{%0,%1,%2,%3}, {%4,%5,%6,%7}, {%8,%9}, {%0,%1,%2,%3};"
        : "+f"(c[0]), "+f"(c[1]), "+f"(c[2]), "+f"(c[3])
        : "r"(a[0]), "r"(a[1]), "r"(a[2]), "r"(a[3]), "r"(b[0]), "r"(b[1]));
}
__device__ __forceinline__ void cpasync16(uint32_t saddr, const void* g) {
    asm volatile("cp.async.cg.shared.global [%0], [%1], 16;"
                 :: "r"(saddr), "l"(g) : "memory");
}
#define CPASYNC_COMMIT() asm volatile("cp.async.commit_group;" ::: "memory")
#define CPASYNC_WAIT0()  asm volatile("cp.async.wait_group 0;" ::: "memory")

#define SWZ128(off) ((off) ^ (((off) >> 3) & 0x70))

// ---------------------------------------------------------------------------
// Scratch (static device globals)
// ---------------------------------------------------------------------------
__device__ float g_lh0[NL * FM];
__device__ float g_lh1[NL * FM];
__device__ float g_lc[NL * FM];
__device__ float g_ch[NC * FM];
__device__ float g_cc[NC * FM];
__device__ float g_buf1[NC * FM];
__device__ float g_buf2[NC * FM];
__device__ float g_msgc[NC * FM];
__device__ float g_msgl[NL * FM];
__device__ float g_v1[NV * 2 * FM];
__device__ float g_v2[NV * 2 * FM];
__device__ float g_logits[NV];
__device__ float g_loss;
__device__ float g_CbI[4 * FM];   // gate-interleaved biases
__device__ float g_LbI[4 * FM];

__device__ int g_lit[NE];
__device__ int g_cnt[NL];
__device__ int g_off[NL + 1];
__device__ int g_ledges[NE];

// weight pool: transposed [N,K] bf16, hi then lo halves
#define WTOT 2228224
__device__ __nv_bfloat16 g_wpool[2 * WTOT];

// ---------------------------------------------------------------------------
// Edge preprocessing (unchanged, known-correct)
// ---------------------------------------------------------------------------
__global__ void edge_prep_kernel(const int* __restrict__ lits) {
    int e = blockIdx.x * blockDim.x + threadIdx.x;
    if (e >= NE) return;
    int v = lits[e];
    int va = (v > 0 ? v : -v) - 1;
    g_lit[e] = (v > 0) ? va : (NV + va);
}
__global__ void zero_cnt_kernel() {
    int i = blockIdx.x * blockDim.x + threadIdx.x;
    if (i < NL) g_cnt[i] = 0;
}
__global__ void count_kernel() {
    int e = blockIdx.x * blockDim.x + threadIdx.x;
    if (e < NE) atomicAdd(&g_cnt[g_lit[e]], 1);
}
__global__ void scan_kernel() {
    __shared__ int part[1024];
    const int t = threadIdx.x;
    const int CH = 8;
    int base = t * CH;
    int local[CH];
    int s = 0;
    #pragma unroll
    for (int i = 0; i < CH; i++) {
        int idx = base + i;
        int v = (idx < NL) ? g_cnt[idx] : 0;
        local[i] = s;
        s += v;
    }
    part[t] = s;
    __syncthreads();
    for (int d = 1; d < 1024; d <<= 1) {
        int v = (t >= d) ? part[t - d] : 0;
        __syncthreads();
        part[t] += v;
        __syncthreads();
    }
    int off = (t == 0) ? 0 : part[t - 1];
    #pragma unroll
    for (int i = 0; i < CH; i++) {
        int idx = base + i;
        if (idx < NL) g_off[idx] = off + local[i];
    }
    if (t == 1023) g_off[NL] = part[1023];
}
__global__ void fill_kernel() {
    int e = blockIdx.x * blockDim.x + threadIdx.x;
    if (e >= NE) return;
    int l = g_lit[e];
    int pos = atomicAdd(&g_cnt[l], 1);
    g_ledges[g_off[l] + pos] = e;
}
__global__ void sort_kernel() {
    int l = blockIdx.x * blockDim.x + threadIdx.x;
    if (l >= NL) return;
    int beg = g_off[l], end = g_off[l + 1];
    for (int i = beg + 1; i < end; i++) {
        int key = g_ledges[i];
        int j = i - 1;
        while (j >= beg && g_ledges[j] > key) {
            g_ledges[j + 1] = g_ledges[j];
            j--;
        }
        g_ledges[j + 1] = key;
    }
}
__global__ void init_state_kernel(const float* __restrict__ Li,
                                  const float* __restrict__ Ci) {
    int idx = blockIdx.x * blockDim.x + threadIdx.x;
    const float inv = 0.0625f;
    if (idx < NL * FM) {
        g_lh0[idx] = Li[idx & (FM - 1)] * inv;
        g_lc[idx] = 0.f;
    }
    if (idx < NC * FM) {
        g_ch[idx] = Ci[idx & (FM - 1)] * inv;
        g_cc[idx] = 0.f;
    }
    if (idx == 0) g_loss = 0.f;
}

// ---------------------------------------------------------------------------
// Weight split+transpose: src fp32 [K,N] -> pool hi/lo bf16 [N,K].
// il != 0: gate-interleave output columns (n -> src col (n&3)*(N/4) + (n>>2)).
// ---------------------------------------------------------------------------
__global__ void wsplit_kernel(const float* __restrict__ src, int K, int N,
                              int off, int il) {
    int idx = blockIdx.x * blockDim.x + threadIdx.x;
    if (idx >= K * N) return;
    int k = idx / N, n = idx - k * N;
    int nsrc = il ? ((n & 3) * (N >> 2) + (n >> 2)) : n;
    float v = src[(size_t)k * N + nsrc];
    __nv_bfloat16 h = __float2bfloat16_rn(v);
    __nv_bfloat16 l = __float2bfloat16_rn(v - __bfloat162float(h));
    g_wpool[off + (size_t)n * K + k] = h;
    g_wpool[WTOT + off + (size_t)n * K + k] = l;
}

// interleave bias [4*FM] -> dst[j] = b[(j&3)*FM + (j>>2)]
__global__ void bint_kernel(const float* __restrict__ b, float* __restrict__ dst) {
    int j = blockIdx.x * blockDim.x + threadIdx.x;
    if (j < 4 * FM) dst[j] = b[(j & 3) * FM + (j >> 2)];
}

// ---------------------------------------------------------------------------
// Pipelined tensor-core GEMM (mma.sync bf16, fp32 accum, Markidis 3-term):
//   C[M,N] = concat_K(A1,A2,A3) @ concat_rows(W1,W2,W3) (+bias)(relu)
// GF_FLIP2: segment-2 rows read flip-permuted (l<NV -> l+NV else l-NV).
// GF_LSTM:  gate-interleaved z; epilogue computes LSTM, writes Hout/Cst.
// ---------------------------------------------------------------------------
#define GF_RELU 1
#define GF_FLIP2 4
#define GF_LSTM 8
#define TG_SMEM 131072

__device__ __forceinline__ float sigm(float x) { return 1.f / (1.f + expf(-x)); }

__global__ __launch_bounds__(256)
void tgemm_kernel(const float* __restrict__ A1, int K1,
                  const __nv_bfloat16* __restrict__ B1h,
                  const __nv_bfloat16* __restrict__ B1l,
                  const float* __restrict__ A2, int K2,
                  const __nv_bfloat16* __restrict__ B2h,
                  const __nv_bfloat16* __restrict__ B2l,
                  const float* __restrict__ A3, int K3,
                  const __nv_bfloat16* __restrict__ B3h,
                  const __nv_bfloat16* __restrict__ B3l,
                  const float* __restrict__ bias, float* __restrict__ C,
                  float* __restrict__ Hout, float* __restrict__ Cst,
                  int M, int N, int flags) {
    extern __shared__ char smem[];
    char* abp[2] = { smem, smem + 32768 };
    const uint32_t sb0 = smem_u32(smem);
    const uint32_t sab[2] = { sb0, sb0 + 32768 };
    const uint32_t sbb[2] = { sb0 + 65536, sb0 + 98304 };

    const int tid = threadIdx.x;
    const int wid = tid >> 5, lid = tid & 31;
    const int bm = blockIdx.y * 128;
    const int bn = blockIdx.x * 128;
    const int wm = (wid & 1) * 64;
    const int wn = (wid >> 1) * 32;

    float acc[4][4][4];
    #pragma unroll
    for (int i = 0; i < 4; i++)
        #pragma unroll
        for (int j = 0; j < 4; j++)
            #pragma unroll
            for (int q = 0; q < 4; q++) acc[i][j][q] = 0.f;

    const int nch = (K1 + K2 + K3) >> 6;
    float4 va[8];

    #define LOAD_A_REGS(c)  do {                                               \
        int kk = (c) << 6;                                                     \
        const float* A = A1; int ldk = K1; int flip = 0;                       \
        if (kk >= K1 + K2) { A = A3; ldk = K3; kk -= K1 + K2; }                \
        else if (kk >= K1) { A = A2; ldk = K2; kk -= K1;                       \
                             flip = (flags & GF_FLIP2); }                      \
        _Pragma("unroll")                                                      \
        for (int i = 0; i < 8; i++) {                                          \
            int idx = i * 256 + tid;                                           \
            int row = idx >> 4;                                                \
            int c4 = (idx & 15) << 2;                                          \
            int gr = bm + row;                                                 \
            va[i] = make_float4(0.f, 0.f, 0.f, 0.f);                           \
            if (gr < M) {                                                      \
                int ar = flip ? (gr < NV ? gr + NV : gr - NV) : gr;            \
                va[i] = *(const float4*)&A[(size_t)ar * ldk + kk + c4];        \
            }                                                                  \
        }                                                                      \
    } while (0)

    #define STORE_A(buf) do {                                                  \
        char* dst = abp[buf];                                                  \
        _Pragma("unroll")                                                      \
        for (int i = 0; i < 8; i++) {                                          \
            int idx = i * 256 + tid;                                           \
            int row = idx >> 4;                                                \
            int c4 = (idx & 15) << 2;                                          \
            float4 v = va[i];                                                  \
            __nv_bfloat16 h0 = __float2bfloat16_rn(v.x);                       \
            __nv_bfloat16 h1 = __float2bfloat16_rn(v.y);                       \
            __nv_bfloat16 h2 = __float2bfloat16_rn(v.z);                       \
            __nv_bfloat16 h3 = __float2bfloat16_rn(v.w);                       \
            __nv_bfloat162 hp0 = __halves2bfloat162(h0, h1);                   \
            __nv_bfloat162 hp1 = __halves2bfloat162(h2, h3);                   \
            __nv_bfloat162 lp0 = __halves2bfloat162(                           \
                __float2bfloat16_rn(v.x - __bfloat162float(h0)),               \
                __float2bfloat16_rn(v.y - __bfloat162float(h1)));              \
            __nv_bfloat162 lp1 = __halves2bfloat162(                           \
                __float2bfloat16_rn(v.z - __bfloat162float(h2)),               \
                __float2bfloat16_rn(v.w - __bfloat162float(h3)));              \
            uint32_t off = SWZ128((uint32_t)(row * 128 + c4 * 2));             \
            *(uint2*)(dst + off) =                                             \
                make_uint2(*(uint32_t*)&hp0, *(uint32_t*)&hp1);                \
            *(uint2*)(dst + 16384 + off) =                                     \
                make_uint2(*(uint32_t*)&lp0, *(uint32_t*)&lp1);                \
        }                                                                      \
    } while (0)

    #define CPASYNC_B(c, buf) do {                                             \
        int kk = (c) << 6;                                                     \
        const __nv_bfloat16 *bh = B1h, *bl = B1l; int ldk = K1;                \
        if (kk >= K1 + K2) { bh = B3h; bl = B3l; ldk = K3; kk -= K1 + K2; }    \
        else if (kk >= K1) { bh = B2h; bl = B2l; ldk = K2; kk -= K1; }         \
        _Pragma("unroll")                                                      \
        for (int i = 0; i < 8; i++) {                                          \
            int idx = i * 256 + tid;                                           \
            int half = idx >> 10;                                              \
            int j = idx & 1023;                                                \
            int row = j >> 3;                                                  \
            int c16 = (j & 7) << 4;                                            \
            const __nv_bfloat16* src =                                         \
                (half ? bl : bh) + (size_t)(bn + row) * ldk + kk + (c16 >> 1); \
            cpasync16(sbb[buf] + half * 16384 +                                \
                      SWZ128((uint32_t)(row * 128 + c16)), src);               \
        }                                                                      \
    } while (0)

    LOAD_A_REGS(0);
    CPASYNC_B(0, 0);
    CPASYNC_COMMIT();
    STORE_A(0);
    CPASYNC_WAIT0();
    __syncthreads();

    for (int c = 0; c < nch; c++) {
        int cur = c & 1, nxt = cur ^ 1;
        if (c + 1 < nch) {
            LOAD_A_REGS(c + 1);
            CPASYNC_B(c + 1, nxt);
            CPASYNC_COMMIT();
        }

        const uint32_t sAh = sab[cur], sAl = sab[cur] + 16384;
        const uint32_t sBh = sbb[cur], sBl = sbb[cur] + 16384;
        #pragma unroll
        for (int s = 0; s < 4; s++) {
            int kb = s * 32;
            uint32_t ah[4][4], al[4][4], bhf[4][2], blf[4][2];
            int arow = (lid & 15);
            int acolb = kb + (lid >> 4) * 16;
            #pragma unroll
            for (int mt = 0; mt < 4; mt++) {
                uint32_t o = SWZ128((uint32_t)((wm + mt * 16 + arow) * 128 + acolb));
                ldsm_x4(ah[mt][0], ah[mt][1], ah[mt][2], ah[mt][3], sAh + o);
                ldsm_x4(al[mt][0], al[mt][1], al[mt][2], al[mt][3], sAl + o);
            }
            int brow = (lid & 7);
            int bcolb = kb + ((lid >> 3) & 1) * 16;
            #pragma unroll
            for (int nt = 0; nt < 4; nt++) {
                uint32_t o = SWZ128((uint32_t)((wn + nt * 8 + brow) * 128 + bcolb));
                ldsm_x2(bhf[nt][0], bhf[nt][1], sBh + o);
                ldsm_x2(blf[nt][0], blf[nt][1], sBl + o);
            }
            #pragma unroll
            for (int mt = 0; mt < 4; mt++)
                #pragma unroll
                for (int nt = 0; nt < 4; nt++) {
                    mma_bf16(acc[mt][nt], ah[mt], bhf[nt]);
                    mma_bf16(acc[mt][nt], al[mt], bhf[nt]);
                    mma_bf16(acc[mt][nt], ah[mt], blf[nt]);
                }
        }

        if (c + 1 < nch) {
            STORE_A(nxt);
            CPASYNC_WAIT0();
        }
        __syncthreads();
    }

    if (flags & GF_LSTM) {
        // ---- fused LSTM epilogue (gate-interleaved z) ----
        float* S = (float*)smem;   // 128 x 132 padded fp32 tile
        #pragma unroll
        for (int mt = 0; mt < 4; mt++) {
            int rr = wm + mt * 16 + (lid >> 2);
            #pragma unroll
            for (int nt = 0; nt < 4; nt++) {
                int cc = wn + nt * 8 + (lid & 3) * 2;
                float bx = bias[bn + cc], by = bias[bn + cc + 1];
                *(float2*)&S[rr * 132 + cc] =
                    make_float2(acc[mt][nt][0] + bx, acc[mt][nt][1] + by);
                *(float2*)&S[(rr + 8) * 132 + cc] =
                    make_float2(acc[mt][nt][2] + bx, acc[mt][nt][3] + by);
            }
        }
        __syncthreads();
        int fbase = bn >> 2;
        #pragma unroll
        for (int i = 0; i < 16; i++) {
            int idx = i * 256 + tid;
            int r = idx >> 5, f = idx & 31;
            int gr = bm + r;
            if (gr < M) {
                float4 z = *(float4*)&S[r * 132 + 4 * f];
                size_t ci = (size_t)gr * FM + fbase + f;
                float cold = Cst[ci];
                float cv = sigm(z.y) * cold + sigm(z.x) * tanhf(z.z);
                Cst[ci] = cv;
                Hout[ci] = sigm(z.w) * tanhf(cv);
            }
        }
        return;
    }

    // ---- normal epilogue: direct float2 stores with bias/relu ----
    #pragma unroll
    for (int mt = 0; mt < 4; mt++) {
        int r0 = bm + wm + mt * 16 + (lid >> 2);
        #pragma unroll
        for (int nt = 0; nt < 4; nt++) {
            int col = bn + wn + nt * 8 + (lid & 3) * 2;
            float bx = 0.f, by = 0.f;
            if (bias) { bx = bias[col]; by = bias[col + 1]; }
            float2 v0 = make_float2(acc[mt][nt][0] + bx, acc[mt][nt][1] + by);
            float2 v1 = make_float2(acc[mt][nt][2] + bx, acc[mt][nt][3] + by);
            if (flags & GF_RELU) {
                v0.x = fmaxf(v0.x, 0.f); v0.y = fmaxf(v0.y, 0.f);
                v1.x = fmaxf(v1.x, 0.f); v1.y = fmaxf(v1.y, 0.f);
            }
            if (r0 < M)     *(float2*)&C[(size_t)r0 * N + col] = v0;
            if (r0 + 8 < M) *(float2*)&C[(size_t)(r0 + 8) * N + col] = v1;
        }
    }
}

// ---------------------------------------------------------------------------
// Gather / vote / loss kernels
// ---------------------------------------------------------------------------
__global__ void clause_gather_kernel(const float* __restrict__ pre,
                                     float* __restrict__ out) {
    int c = blockIdx.x;
    int f = threadIdx.x;
    int e0 = c * 3;
    float s = pre[(size_t)g_lit[e0] * FM + f] +
              pre[(size_t)g_lit[e0 + 1] * FM + f] +
              pre[(size_t)g_lit[e0 + 2] * FM + f];
    out[(size_t)c * FM + f] = s;
}

__global__ void lit_gather_kernel(const float* __restrict__ cl_pre,
                                  float* __restrict__ msgl) {
    int l = blockIdx.x;
    int f = threadIdx.x;
    int beg = g_off[l], end = g_off[l + 1];
    float s = 0.f;
    for (int i = beg; i < end; i++) {
        int e = g_ledges[i];
        s += cl_pre[(size_t)(e / 3) * FM + f];
    }
    msgl[(size_t)l * FM + f] = s;
}

__global__ void vote_out_kernel(const float* __restrict__ H,
                                const float* __restrict__ W,
                                const float* __restrict__ b) {
    int r = blockIdx.x;
    float s = 0.f;
    for (int k = threadIdx.x; k < 2 * FM; k += blockDim.x)
        s += H[(size_t)r * 2 * FM + k] * W[k];
    for (int o = 16; o; o >>= 1) s += __shfl_down_sync(0xffffffffu, s, o);
    __shared__ float sm[4];
    if ((threadIdx.x & 31) == 0) sm[threadIdx.x >> 5] = s;
    __syncthreads();
    if (threadIdx.x == 0)
        g_logits[r] = sm[0] + sm[1] + sm[2] + sm[3] + b[0];
}

__device__ __forceinline__ float softplus_f(float x) {
    return x > 0.f ? x + log1pf(expf(-x)) : log1pf(expf(x));
}

__global__ void loss_kernel() {
    int c = blockIdx.x * blockDim.x + threadIdx.x;
    float t = 0.f;
    if (c < NC) {
        float s = 0.f;
        #pragma unroll
        for (int k = 0; k < 3; k++) {
            int lit = g_lit[c * 3 + k];
            float sign = (lit < NV) ? 1.f : -1.f;
            int var = (lit < NV) ? lit : lit - NV;
            s += softplus_f(g_logits[var] * sign);
        }
        float cv = expf(-s);
        float l = -logf(1.f - cv + 1e-8f);
        t = l * l;
    }
    for (int o = 16; o; o >>= 1) t += __shfl_down_sync(0xffffffffu, t, o);
    __shared__ float sm[8];
    if ((threadIdx.x & 31) == 0) sm[threadIdx.x >> 5] = t;
    __syncthreads();
    if (threadIdx.x < 8) {
        float v = sm[threadIdx.x];
        for (int o = 4; o; o >>= 1) v += __shfl_down_sync(0xffu, v, o);
        if (threadIdx.x == 0) atomicAdd(&g_loss, v);
    }
}

__global__ void finalize_kernel(float* __restrict__ out, int out_size) {
    int i = blockIdx.x * blockDim.x + threadIdx.x;
    if (i < NV && i < out_size) out[i] = g_logits[i];
    if (i == 0 && out_size > NV) out[NV] = g_loss / (float)ROUNDS;
}

// ---------------------------------------------------------------------------
// Host orchestration
// ---------------------------------------------------------------------------
static const __nv_bfloat16* g_wp_host;

static inline void launch_tg(const float* A1, int K1, int off1,
                             const float* A2, int K2, int off2,
                             const float* A3, int K3, int off3,
                             const float* bias, float* C,
                             float* Hout, float* Cst,
                             int M, int N, int flags) {
    const __nv_bfloat16* wp = g_wp_host;
    dim3 grid(N / 128, (M + 127) / 128);
    tgemm_kernel<<<grid, 256, TG_SMEM>>>(
        A1, K1, wp + off1, wp + WTOT + off1,
        A2, K2, A2 ? wp + off2 : nullptr, A2 ? wp + WTOT + off2 : nullptr,
        A3, K3, A3 ? wp + off3 : nullptr, A3 ? wp + WTOT + off3 : nullptr,
        bias, C, Hout, Cst, M, N, flags);
}

extern "C" void kernel_launch(void* const* d_in, const int* in_sizes, int n_in,
                              void* d_out, int out_size) {
    int base = (n_in >= 2 && in_sizes[1] == 1) ? 1 : 0;
    const int* clause_lits = (const int*)d_in[0];
    const float* P[26];
    for (int i = 0; i < 26; i++) P[i] = (const float*)d_in[1 + base + i];
    const float *L_init = P[0], *C_init = P[1];
    const float *LC_W0 = P[2], *LC_b0 = P[3], *LC_W1 = P[4], *LC_b1 = P[5],
                *LC_W2 = P[6], *LC_b2 = P[7];
    const float *CL_W0 = P[8], *CL_b0 = P[9], *CL_W1 = P[10], *CL_b1 = P[11],
                *CL_W2 = P[12], *CL_b2 = P[13];
    const float *C_Wx = P[14], *C_Wh = P[15], *C_b = P[16];
    const float *L_Wx = P[17], *L_Wh = P[18], *L_b = P[19];
    const float *V_W0 = P[20], *V_b0 = P[21], *V_W1 = P[22], *V_b1 = P[23],
                *V_W2 = P[24], *V_b2 = P[25];

    float *lh0, *lh1, *lc, *ch, *cc, *buf1, *buf2, *msgc, *msgl, *v1, *v2;
    float *CbI, *LbI;
    __nv_bfloat16* wp;
    cudaGetSymbolAddress((void**)&lh0, g_lh0);
    cudaGetSymbolAddress((void**)&lh1, g_lh1);
    cudaGetSymbolAddress((void**)&lc, g_lc);
    cudaGetSymbolAddress((void**)&ch, g_ch);
    cudaGetSymbolAddress((void**)&cc, g_cc);
    cudaGetSymbolAddress((void**)&buf1, g_buf1);
    cudaGetSymbolAddress((void**)&buf2, g_buf2);
    cudaGetSymbolAddress((void**)&msgc, g_msgc);
    cudaGetSymbolAddress((void**)&msgl, g_msgl);
    cudaGetSymbolAddress((void**)&v1, g_v1);
    cudaGetSymbolAddress((void**)&v2, g_v2);
    cudaGetSymbolAddress((void**)&CbI, g_CbI);
    cudaGetSymbolAddress((void**)&LbI, g_LbI);
    cudaGetSymbolAddress((void**)&wp, g_wpool);
    g_wp_host = wp;

    cudaFuncSetAttribute(tgemm_kernel, cudaFuncAttributeMaxDynamicSharedMemorySize,
                         TG_SMEM);

    // weight pool offsets ([N,K] transposed, element offsets)
    const int oLC0 = 0, oLC1 = 65536, oLC2 = 131072;
    const int oCL0 = 196608, oCL1 = 262144, oCL2 = 327680;
    const int oCWx = 393216, oCWh = 655360;
    const int oLWxa = 917504, oLWxb = 1179648, oLWh = 1441792;
    const int oVW0a = 1703936, oVW0b = 1835008, oVW1 = 1966080;

    struct { const float* src; int K, N, off, il; } WS[14] = {
        {LC_W0, 256, 256, oLC0, 0}, {LC_W1, 256, 256, oLC1, 0},
        {LC_W2, 256, 256, oLC2, 0},
        {CL_W0, 256, 256, oCL0, 0}, {CL_W1, 256, 256, oCL1, 0},
        {CL_W2, 256, 256, oCL2, 0},
        {C_Wx, 256, 1024, oCWx, 1}, {C_Wh, 256, 1024, oCWh, 1},
        {L_Wx, 256, 1024, oLWxa, 1}, {L_Wx + 256 * 1024, 256, 1024, oLWxb, 1},
        {L_Wh, 256, 1024, oLWh, 1},
        {V_W0, 256, 512, oVW0a, 0}, {V_W0 + 256 * 512, 256, 512, oVW0b, 0},
        {V_W1, 512, 512, oVW1, 0},
    };

    // ---- launch ordering: indices 0-4 are the minimal deps of the first GEMM,
    // so that ncu (-s 5 -c 1) profiles a tgemm launch (index 5). ----
    {
        int n0 = WS[0].K * WS[0].N;                                         // 0
        wsplit_kernel<<<(n0 + 255) / 256, 256>>>(WS[0].src, WS[0].K, WS[0].N,
                                                 WS[0].off, WS[0].il);
        init_state_kernel<<<(NC * FM + 255) / 256, 256>>>(L_init, C_init);  // 1
        edge_prep_kernel<<<(NE + 255) / 256, 256>>>(clause_lits);           // 2
        zero_cnt_kernel<<<(NL + 255) / 256, 256>>>();                       // 3
        count_kernel<<<(NE + 255) / 256, 256>>>();                          // 4
    }
    // 5: first GEMM of round 1 (profiled by ncu)
    launch_tg(lh0, 256, oLC0, nullptr, 0, 0, nullptr, 0, 0,
              LC_b0, buf1, nullptr, nullptr, NL, 256, GF_RELU);
    // remaining preprocessing
    scan_kernel<<<1, 1024>>>();
    zero_cnt_kernel<<<(NL + 255) / 256, 256>>>();
    fill_kernel<<<(NE + 255) / 256, 256>>>();
    sort_kernel<<<(NL + 127) / 128, 128>>>();
    for (int i = 1; i < 14; i++) {
        int n = WS[i].K * WS[i].N;
        wsplit_kernel<<<(n + 255) / 256, 256>>>(WS[i].src, WS[i].K, WS[i].N,
                                                WS[i].off, WS[i].il);
    }
    bint_kernel<<<4, 256>>>(C_b, CbI);
    bint_kernel<<<4, 256>>>(L_b, LbI);

    float* lhbuf[2] = { lh0, lh1 };
    for (int r = 0; r < ROUNDS; r++) {
        const float* lhr = lhbuf[r & 1];
        float* lhw = lhbuf[(r + 1) & 1];

        // literal -> clause MLP (layer 0 of round 0 already launched above)
        if (r > 0)
            launch_tg(lhr, 256, oLC0, nullptr, 0, 0, nullptr, 0, 0,
                      LC_b0, buf1, nullptr, nullptr, NL, 256, GF_RELU);
        launch_tg(buf1, 256, oLC1, nullptr, 0, 0, nullptr, 0, 0,
                  LC_b1, buf2, nullptr, nullptr, NL, 256, GF_RELU);
        launch_tg(buf2, 256, oLC2, nullptr, 0, 0, nullptr, 0, 0,
                  LC_b2, buf1, nullptr, nullptr, NL, 256, 0);
        clause_gather_kernel<<<NC, FM>>>(buf1, msgc);

        // clause LSTM (fused GEMM + LSTM epilogue; ch in-place, cc in-place)
        launch_tg(msgc, 256, oCWx, ch, 256, oCWh, nullptr, 0, 0,
                  CbI, nullptr, ch, cc, NC, 1024, GF_LSTM);

        // clause -> literal MLP
        launch_tg(ch, 256, oCL0, nullptr, 0, 0, nullptr, 0, 0,
                  CL_b0, buf1, nullptr, nullptr, NC, 256, GF_RELU);
        launch_tg(buf1, 256, oCL1, nullptr, 0, 0, nullptr, 0, 0,
                  CL_b1, buf2, nullptr, nullptr, NC, 256, GF_RELU);
        launch_tg(buf2, 256, oCL2, nullptr, 0, 0, nullptr, 0, 0,
                  CL_b2, buf1, nullptr, nullptr, NC, 256, 0);
        lit_gather_kernel<<<NL, FM>>>(buf1, msgl);

        // literal LSTM: z = [msgl, flipped(lh), lh]; writes lh_new (ping-pong)
        launch_tg(msgl, 256, oLWxa, lhr, 256, oLWxb, lhr, 256, oLWh,
                  LbI, nullptr, lhw, lc, NL, 1024, GF_LSTM | GF_FLIP2);

        // vote: x = [lh_new[:NV], lh_new[NV:]] along K
        launch_tg(lhw, 256, oVW0a, lhw + (size_t)NV * FM, 256, oVW0b,
                  nullptr, 0, 0, V_b0, v1, nullptr, nullptr, NV, 512, GF_RELU);
        launch_tg(v1, 512, oVW1, nullptr, 0, 0, nullptr, 0, 0,
                  V_b1, v2, nullptr, nullptr, NV, 512, GF_RELU);
        vote_out_kernel<<<NV, 128>>>(v2, V_W2, V_b2);
        loss_kernel<<<(NC + 255) / 256, 256>>>();
    }

    finalize_kernel<<<(NV + 255) / 256, 256>>>((float*)d_out, out_size);
}

// round 11
// speedup vs baseline: 1.0589x; 1.0589x over previous
#include <cuda_runtime.h>
#include <cuda_bf16.h>
#include <math.h>
#include <stdint.h>

#define NV 4000
#define NL 8000          // 2*NV literals
#define NC 16800
#define NE 50400         // NC*3 edges
#define FM 256
#define ROUNDS 32
#define VCH 8            // rounds per batched-vote chunk
#define VM (VCH * NV)    // 32000 rows per vote chunk

// ---------------------------------------------------------------------------
// PTX helpers (baseline ISA only: ldmatrix + mma.sync + cp.async, sm_80+)
// ---------------------------------------------------------------------------
__device__ __forceinline__ uint32_t smem_u32(const void* p) {
    uint32_t a;
    asm("{ .reg .u64 t; cvta.to.shared.u64 t, %1; cvt.u32.u64 %0, t; }"
        : "=r"(a) : "l"(p));
    return a;
}
__device__ __forceinline__ void ldsm_x4(uint32_t& r0, uint32_t& r1,
                                        uint32_t& r2, uint32_t& r3, uint32_t a) {
    asm volatile("ldmatrix.sync.aligned.m8n8.x4.shared.b16 {%0,%1,%2,%3}, [%4];"
                 : "=r"(r0), "=r"(r1), "=r"(r2), "=r"(r3) : "r"(a));
}
__device__ __forceinline__ void ldsm_x2(uint32_t& r0, uint32_t& r1, uint32_t a) {
    asm volatile("ldmatrix.sync.aligned.m8n8.x2.shared.b16 {%0,%1}, [%2];"
                 : "=r"(r0), "=r"(r1) : "r"(a));
}
__device__ __forceinline__ void mma_bf16(float* c, const uint32_t* a,
                                         const uint32_t* b) {
    asm volatile(
        "mma.sync.aligned.m16n8k16.row.col.f32.bf16.bf16.f32 "
        "{%0,%1,%2,%3}, {%4,%5,%6,%7}, {%8,%9}, {%0,%1,%2,%3};"
        : "+f"(c[0]), "+f"(c[1]), "+f"(c[2]), "+f"(c[3])
        : "r"(a[0]), "r"(a[1]), "r"(a[2]), "r"(a[3]), "r"(b[0]), "r"(b[1]));
}
__device__ __forceinline__ void cpasync16(uint32_t saddr, const void* g) {
    asm volatile("cp.async.cg.shared.global [%0], [%1], 16;"
                 :: "r"(saddr), "l"(g) : "memory");
}
#define CPASYNC_COMMIT() asm volatile("cp.async.commit_group;" ::: "memory")
#define CPASYNC_WAIT0()  asm volatile("cp.async.wait_group 0;" ::: "memory")

#define SWZ128(off) ((off) ^ (((off) >> 3) & 0x70))

// ---------------------------------------------------------------------------
// Scratch (static device globals)
// ---------------------------------------------------------------------------
__device__ float g_lha[(ROUNDS + 1) * NL * FM];   // lh history, slot r = state after round r
__device__ float g_lc[NL * FM];
__device__ float g_ch[NC * FM];
__device__ float g_cc[NC * FM];
__device__ float g_buf1[NC * FM];
__device__ float g_buf2[NC * FM];
__device__ float g_msgc[NC * FM];
__device__ float g_zc[NC * 4 * FM];
__device__ float g_msgl[NL * FM];
__device__ float g_zl[NL * 4 * FM];
__device__ float g_v1[VM * 2 * FM];
__device__ float g_v2[VM * 2 * FM];
__device__ float g_logitsA[ROUNDS * NV];
__device__ float g_loss;

__device__ int g_lit[NE];
__device__ int g_cnt[NL];
__device__ int g_off[NL + 1];
__device__ int g_ledges[NE];

// weight pool: transposed [N,K] bf16, hi then lo halves
#define WTOT 2228224
__device__ __nv_bfloat16 g_wpool[2 * WTOT];

// ---------------------------------------------------------------------------
// Edge preprocessing (unchanged, known-correct)
// ---------------------------------------------------------------------------
__global__ void edge_prep_kernel(const int* __restrict__ lits) {
    int e = blockIdx.x * blockDim.x + threadIdx.x;
    if (e >= NE) return;
    int v = lits[e];
    int va = (v > 0 ? v : -v) - 1;
    g_lit[e] = (v > 0) ? va : (NV + va);
}
__global__ void zero_cnt_kernel() {
    int i = blockIdx.x * blockDim.x + threadIdx.x;
    if (i < NL) g_cnt[i] = 0;
}
__global__ void count_kernel() {
    int e = blockIdx.x * blockDim.x + threadIdx.x;
    if (e < NE) atomicAdd(&g_cnt[g_lit[e]], 1);
}
__global__ void scan_kernel() {
    __shared__ int part[1024];
    const int t = threadIdx.x;
    const int CH = 8;
    int base = t * CH;
    int local[CH];
    int s = 0;
    #pragma unroll
    for (int i = 0; i < CH; i++) {
        int idx = base + i;
        int v = (idx < NL) ? g_cnt[idx] : 0;
        local[i] = s;
        s += v;
    }
    part[t] = s;
    __syncthreads();
    for (int d = 1; d < 1024; d <<= 1) {
        int v = (t >= d) ? part[t - d] : 0;
        __syncthreads();
        part[t] += v;
        __syncthreads();
    }
    int off = (t == 0) ? 0 : part[t - 1];
    #pragma unroll
    for (int i = 0; i < CH; i++) {
        int idx = base + i;
        if (idx < NL) g_off[idx] = off + local[i];
    }
    if (t == 1023) g_off[NL] = part[1023];
}
__global__ void fill_kernel() {
    int e = blockIdx.x * blockDim.x + threadIdx.x;
    if (e >= NE) return;
    int l = g_lit[e];
    int pos = atomicAdd(&g_cnt[l], 1);
    g_ledges[g_off[l] + pos] = e;
}
__global__ void sort_kernel() {
    int l = blockIdx.x * blockDim.x + threadIdx.x;
    if (l >= NL) return;
    int beg = g_off[l], end = g_off[l + 1];
    for (int i = beg + 1; i < end; i++) {
        int key = g_ledges[i];
        int j = i - 1;
        while (j >= beg && g_ledges[j] > key) {
            g_ledges[j + 1] = g_ledges[j];
            j--;
        }
        g_ledges[j + 1] = key;
    }
}
__global__ void init_state_kernel(const float* __restrict__ Li,
                                  const float* __restrict__ Ci) {
    int idx = blockIdx.x * blockDim.x + threadIdx.x;
    const float inv = 0.0625f;
    if (idx < NL * FM) {
        g_lha[idx] = Li[idx & (FM - 1)] * inv;   // slot 0
        g_lc[idx] = 0.f;
    }
    if (idx < NC * FM) {
        g_ch[idx] = Ci[idx & (FM - 1)] * inv;
        g_cc[idx] = 0.f;
    }
    if (idx == 0) g_loss = 0.f;
}

// ---------------------------------------------------------------------------
// Weight split+transpose: src fp32 [K,N] -> pool hi/lo bf16 [N,K]
// ---------------------------------------------------------------------------
__global__ void wsplit_kernel(const float* __restrict__ src, int K, int N, int off) {
    int idx = blockIdx.x * blockDim.x + threadIdx.x;
    if (idx >= K * N) return;
    int k = idx / N, n = idx - k * N;
    float v = src[idx];
    __nv_bfloat16 h = __float2bfloat16_rn(v);
    __nv_bfloat16 l = __float2bfloat16_rn(v - __bfloat162float(h));
    g_wpool[off + (size_t)n * K + k] = h;
    g_wpool[WTOT + off + (size_t)n * K + k] = l;
}

// ---------------------------------------------------------------------------
// Pipelined tensor-core GEMM (mma.sync bf16, fp32 accum, Markidis 3-term):
//   C[M,N] = concat_K(A1,A2,A3) @ concat_rows(W1,W2,W3) (+bias)(relu)
// GF_FLIP2:   segment-2 rows read flip-permuted (l<NV -> l+NV else l-NV).
// GF_VOTEMAP: row m -> lh slot m/NV, var m%NV (A2 pointer pre-offset by NV*FM).
// ---------------------------------------------------------------------------
#define GF_RELU 1
#define GF_FLIP2 4
#define GF_VOTEMAP 8
#define TG_SMEM 131072

__global__ __launch_bounds__(256)
void tgemm_kernel(const float* __restrict__ A1, int K1,
                  const __nv_bfloat16* __restrict__ B1h,
                  const __nv_bfloat16* __restrict__ B1l,
                  const float* __restrict__ A2, int K2,
                  const __nv_bfloat16* __restrict__ B2h,
                  const __nv_bfloat16* __restrict__ B2l,
                  const float* __restrict__ A3, int K3,
                  const __nv_bfloat16* __restrict__ B3h,
                  const __nv_bfloat16* __restrict__ B3l,
                  const float* __restrict__ bias, float* __restrict__ C,
                  int M, int N, int flags) {
    extern __shared__ char smem[];
    char* abp[2] = { smem, smem + 32768 };
    const uint32_t sb0 = smem_u32(smem);
    const uint32_t sab[2] = { sb0, sb0 + 32768 };
    const uint32_t sbb[2] = { sb0 + 65536, sb0 + 98304 };

    const int tid = threadIdx.x;
    const int wid = tid >> 5, lid = tid & 31;
    const int bm = blockIdx.y * 128;
    const int bn = blockIdx.x * 128;
    const int wm = (wid & 1) * 64;
    const int wn = (wid >> 1) * 32;

    float acc[4][4][4];
    #pragma unroll
    for (int i = 0; i < 4; i++)
        #pragma unroll
        for (int j = 0; j < 4; j++)
            #pragma unroll
            for (int q = 0; q < 4; q++) acc[i][j][q] = 0.f;

    const int nch = (K1 + K2 + K3) >> 6;
    float4 va[8];

    #define LOAD_A_REGS(c)  do {                                               \
        int kk = (c) << 6;                                                     \
        const float* A = A1; int ldk = K1; int flip = 0;                       \
        if (kk >= K1 + K2) { A = A3; ldk = K3; kk -= K1 + K2; }                \
        else if (kk >= K1) { A = A2; ldk = K2; kk -= K1;                       \
                             flip = (flags & GF_FLIP2); }                      \
        _Pragma("unroll")                                                      \
        for (int i = 0; i < 8; i++) {                                          \
            int idx = i * 256 + tid;                                           \
            int row = idx >> 4;                                                \
            int c4 = (idx & 15) << 2;                                          \
            int gr = bm + row;                                                 \
            va[i] = make_float4(0.f, 0.f, 0.f, 0.f);                           \
            if (gr < M) {                                                      \
                int ar = gr;                                                   \
                if (flip) ar = (gr < NV) ? gr + NV : gr - NV;                  \
                if (flags & GF_VOTEMAP) {                                      \
                    int q = gr / NV;                                           \
                    ar = q * NL + (gr - q * NV);                               \
                }                                                              \
                va[i] = *(const float4*)&A[(size_t)ar * ldk + kk + c4];        \
            }                                                                  \
        }                                                                      \
    } while (0)

    #define STORE_A(buf) do {                                                  \
        char* dst = abp[buf];                                                  \
        _Pragma("unroll")                                                      \
        for (int i = 0; i < 8; i++) {                                          \
            int idx = i * 256 + tid;                                           \
            int row = idx >> 4;                                                \
            int c4 = (idx & 15) << 2;                                          \
            float4 v = va[i];                                                  \
            __nv_bfloat16 h0 = __float2bfloat16_rn(v.x);                       \
            __nv_bfloat16 h1 = __float2bfloat16_rn(v.y);                       \
            __nv_bfloat16 h2 = __float2bfloat16_rn(v.z);                       \
            __nv_bfloat16 h3 = __float2bfloat16_rn(v.w);                       \
            __nv_bfloat162 hp0 = __halves2bfloat162(h0, h1);                   \
            __nv_bfloat162 hp1 = __halves2bfloat162(h2, h3);                   \
            __nv_bfloat162 lp0 = __halves2bfloat162(                           \
                __float2bfloat16_rn(v.x - __bfloat162float(h0)),               \
                __float2bfloat16_rn(v.y - __bfloat162float(h1)));              \
            __nv_bfloat162 lp1 = __halves2bfloat162(                           \
                __float2bfloat16_rn(v.z - __bfloat162float(h2)),               \
                __float2bfloat16_rn(v.w - __bfloat162float(h3)));              \
            uint32_t off = SWZ128((uint32_t)(row * 128 + c4 * 2));             \
            *(uint2*)(dst + off) =                                             \
                make_uint2(*(uint32_t*)&hp0, *(uint32_t*)&hp1);                \
            *(uint2*)(dst + 16384 + off) =                                     \
                make_uint2(*(uint32_t*)&lp0, *(uint32_t*)&lp1);                \
        }                                                                      \
    } while (0)

    #define CPASYNC_B(c, buf) do {                                             \
        int kk = (c) << 6;                                                     \
        const __nv_bfloat16 *bh = B1h, *bl = B1l; int ldk = K1;                \
        if (kk >= K1 + K2) { bh = B3h; bl = B3l; ldk = K3; kk -= K1 + K2; }    \
        else if (kk >= K1) { bh = B2h; bl = B2l; ldk = K2; kk -= K1; }         \
        _Pragma("unroll")                                                      \
        for (int i = 0; i < 8; i++) {                                          \
            int idx = i * 256 + tid;                                           \
            int half = idx >> 10;                                              \
            int j = idx & 1023;                                                \
            int row = j >> 3;                                                  \
            int c16 = (j & 7) << 4;                                            \
            const __nv_bfloat16* src =                                         \
                (half ? bl : bh) + (size_t)(bn + row) * ldk + kk + (c16 >> 1); \
            cpasync16(sbb[buf] + half * 16384 +                                \
                      SWZ128((uint32_t)(row * 128 + c16)), src);               \
        }                                                                      \
    } while (0)

    LOAD_A_REGS(0);
    CPASYNC_B(0, 0);
    CPASYNC_COMMIT();
    STORE_A(0);
    CPASYNC_WAIT0();
    __syncthreads();

    for (int c = 0; c < nch; c++) {
        int cur = c & 1, nxt = cur ^ 1;
        if (c + 1 < nch) {
            LOAD_A_REGS(c + 1);
            CPASYNC_B(c + 1, nxt);
            CPASYNC_COMMIT();
        }

        const uint32_t sAh = sab[cur], sAl = sab[cur] + 16384;
        const uint32_t sBh = sbb[cur], sBl = sbb[cur] + 16384;
        #pragma unroll
        for (int s = 0; s < 4; s++) {
            int kb = s * 32;
            uint32_t ah[4][4], al[4][4], bhf[4][2], blf[4][2];
            int arow = (lid & 15);
            int acolb = kb + (lid >> 4) * 16;
            #pragma unroll
            for (int mt = 0; mt < 4; mt++) {
                uint32_t o = SWZ128((uint32_t)((wm + mt * 16 + arow) * 128 + acolb));
                ldsm_x4(ah[mt][0], ah[mt][1], ah[mt][2], ah[mt][3], sAh + o);
                ldsm_x4(al[mt][0], al[mt][1], al[mt][2], al[mt][3], sAl + o);
            }
            int brow = (lid & 7);
            int bcolb = kb + ((lid >> 3) & 1) * 16;
            #pragma unroll
            for (int nt = 0; nt < 4; nt++) {
                uint32_t o = SWZ128((uint32_t)((wn + nt * 8 + brow) * 128 + bcolb));
                ldsm_x2(bhf[nt][0], bhf[nt][1], sBh + o);
                ldsm_x2(blf[nt][0], blf[nt][1], sBl + o);
            }
            #pragma unroll
            for (int mt = 0; mt < 4; mt++)
                #pragma unroll
                for (int nt = 0; nt < 4; nt++) {
                    mma_bf16(acc[mt][nt], ah[mt], bhf[nt]);
                    mma_bf16(acc[mt][nt], al[mt], bhf[nt]);
                    mma_bf16(acc[mt][nt], ah[mt], blf[nt]);
                }
        }

        if (c + 1 < nch) {
            STORE_A(nxt);
            CPASYNC_WAIT0();
        }
        __syncthreads();
    }

    // ---- epilogue: direct float2 stores with bias/relu ----
    #pragma unroll
    for (int mt = 0; mt < 4; mt++) {
        int r0 = bm + wm + mt * 16 + (lid >> 2);
        #pragma unroll
        for (int nt = 0; nt < 4; nt++) {
            int col = bn + wn + nt * 8 + (lid & 3) * 2;
            float bx = 0.f, by = 0.f;
            if (bias) { bx = bias[col]; by = bias[col + 1]; }
            float2 v0 = make_float2(acc[mt][nt][0] + bx, acc[mt][nt][1] + by);
            float2 v1 = make_float2(acc[mt][nt][2] + bx, acc[mt][nt][3] + by);
            if (flags & GF_RELU) {
                v0.x = fmaxf(v0.x, 0.f); v0.y = fmaxf(v0.y, 0.f);
                v1.x = fmaxf(v1.x, 0.f); v1.y = fmaxf(v1.y, 0.f);
            }
            if (r0 < M)     *(float2*)&C[(size_t)r0 * N + col] = v0;
            if (r0 + 8 < M) *(float2*)&C[(size_t)(r0 + 8) * N + col] = v1;
        }
    }
}

// ---------------------------------------------------------------------------
// Elementwise / gather kernels
// ---------------------------------------------------------------------------
__device__ __forceinline__ float sigm(float x) { return 1.f / (1.f + expf(-x)); }

// LSTM elementwise: reads z (gate-blocked cols) and c; writes c and h_out.
__global__ void lstm_kernel(const float* __restrict__ z,
                            float* __restrict__ hout,
                            float* __restrict__ c, int R) {
    int idx = blockIdx.x * blockDim.x + threadIdx.x;
    if (idx >= R * FM) return;
    int r = idx / FM, f = idx - r * FM;
    const float* zr = z + (size_t)r * 4 * FM;
    float zi = zr[f], zf = zr[FM + f], zg = zr[2 * FM + f], zo = zr[3 * FM + f];
    float cv = sigm(zf) * c[idx] + sigm(zi) * tanhf(zg);
    c[idx] = cv;
    hout[idx] = sigm(zo) * tanhf(cv);
}

__global__ void clause_gather_kernel(const float* __restrict__ pre,
                                     float* __restrict__ out) {
    int c = blockIdx.x;
    int f = threadIdx.x;
    int e0 = c * 3;
    float s = pre[(size_t)g_lit[e0] * FM + f] +
              pre[(size_t)g_lit[e0 + 1] * FM + f] +
              pre[(size_t)g_lit[e0 + 2] * FM + f];
    out[(size_t)c * FM + f] = s;
}

__global__ void lit_gather_kernel(const float* __restrict__ cl_pre,
                                  float* __restrict__ msgl) {
    int l = blockIdx.x;
    int f = threadIdx.x;
    int beg = g_off[l], end = g_off[l + 1];
    float s = 0.f;
    for (int i = beg; i < end; i++) {
        int e = g_ledges[i];
        s += cl_pre[(size_t)(e / 3) * FM + f];
    }
    msgl[(size_t)l * FM + f] = s;
}

// batched: logits_out[r] = H[r,:] . W[:,0] + b[0], r over VM rows
__global__ void vote_out_kernel(const float* __restrict__ H,
                                const float* __restrict__ W,
                                const float* __restrict__ b,
                                float* __restrict__ lo) {
    int r = blockIdx.x;
    float s = 0.f;
    for (int k = threadIdx.x; k < 2 * FM; k += blockDim.x)
        s += H[(size_t)r * 2 * FM + k] * W[k];
    for (int o = 16; o; o >>= 1) s += __shfl_down_sync(0xffffffffu, s, o);
    __shared__ float sm[4];
    if ((threadIdx.x & 31) == 0) sm[threadIdx.x >> 5] = s;
    __syncthreads();
    if (threadIdx.x == 0)
        lo[r] = sm[0] + sm[1] + sm[2] + sm[3] + b[0];
}

__device__ __forceinline__ float softplus_f(float x) {
    return x > 0.f ? x + log1pf(expf(-x)) : log1pf(expf(x));
}

// batched: VCH rounds of clause loss; lo = logits [VCH*NV]
__global__ void loss_kernel(const float* __restrict__ lo) {
    int idx = blockIdx.x * blockDim.x + threadIdx.x;
    float t = 0.f;
    if (idx < VCH * NC) {
        int q = idx / NC, c = idx - q * NC;
        const float* lg = lo + q * NV;
        float s = 0.f;
        #pragma unroll
        for (int k = 0; k < 3; k++) {
            int lit = g_lit[c * 3 + k];
            float sign = (lit < NV) ? 1.f : -1.f;
            int var = (lit < NV) ? lit : lit - NV;
            s += softplus_f(lg[var] * sign);
        }
        float cv = expf(-s);
        float l = -logf(1.f - cv + 1e-8f);
        t = l * l;
    }
    for (int o = 16; o; o >>= 1) t += __shfl_down_sync(0xffffffffu, t, o);
    __shared__ float sm[8];
    if ((threadIdx.x & 31) == 0) sm[threadIdx.x >> 5] = t;
    __syncthreads();
    if (threadIdx.x < 8) {
        float v = sm[threadIdx.x];
        for (int o = 4; o; o >>= 1) v += __shfl_down_sync(0xffu, v, o);
        if (threadIdx.x == 0) atomicAdd(&g_loss, v);
    }
}

__global__ void finalize_kernel(float* __restrict__ out, int out_size) {
    int i = blockIdx.x * blockDim.x + threadIdx.x;
    if (i < NV && i < out_size) out[i] = g_logitsA[(ROUNDS - 1) * NV + i];
    if (i == 0 && out_size > NV) out[NV] = g_loss / (float)ROUNDS;
}

// ---------------------------------------------------------------------------
// Host orchestration
// ---------------------------------------------------------------------------
static const __nv_bfloat16* g_wp_host;

static inline void launch_tg(const float* A1, int K1, int off1,
                             const float* A2, int K2, int off2,
                             const float* A3, int K3, int off3,
                             const float* bias, float* C, int M, int N, int flags) {
    const __nv_bfloat16* wp = g_wp_host;
    dim3 grid(N / 128, (M + 127) / 128);
    tgemm_kernel<<<grid, 256, TG_SMEM>>>(
        A1, K1, wp + off1, wp + WTOT + off1,
        A2, K2, A2 ? wp + off2 : nullptr, A2 ? wp + WTOT + off2 : nullptr,
        A3, K3, A3 ? wp + off3 : nullptr, A3 ? wp + WTOT + off3 : nullptr,
        bias, C, M, N, flags);
}

extern "C" void kernel_launch(void* const* d_in, const int* in_sizes, int n_in,
                              void* d_out, int out_size) {
    int base = (n_in >= 2 && in_sizes[1] == 1) ? 1 : 0;
    const int* clause_lits = (const int*)d_in[0];
    const float* P[26];
    for (int i = 0; i < 26; i++) P[i] = (const float*)d_in[1 + base + i];
    const float *L_init = P[0], *C_init = P[1];
    const float *LC_W0 = P[2], *LC_b0 = P[3], *LC_W1 = P[4], *LC_b1 = P[5],
                *LC_W2 = P[6], *LC_b2 = P[7];
    const float *CL_W0 = P[8], *CL_b0 = P[9], *CL_W1 = P[10], *CL_b1 = P[11],
                *CL_W2 = P[12], *CL_b2 = P[13];
    const float *C_Wx = P[14], *C_Wh = P[15], *C_b = P[16];
    const float *L_Wx = P[17], *L_Wh = P[18], *L_b = P[19];
    const float *V_W0 = P[20], *V_b0 = P[21], *V_W1 = P[22], *V_b1 = P[23],
                *V_W2 = P[24], *V_b2 = P[25];

    float *lha, *lc, *ch, *cc, *buf1, *buf2, *msgc, *zc, *msgl, *zl, *v1, *v2;
    float *logitsA;
    __nv_bfloat16* wp;
    cudaGetSymbolAddress((void**)&lha, g_lha);
    cudaGetSymbolAddress((void**)&lc, g_lc);
    cudaGetSymbolAddress((void**)&ch, g_ch);
    cudaGetSymbolAddress((void**)&cc, g_cc);
    cudaGetSymbolAddress((void**)&buf1, g_buf1);
    cudaGetSymbolAddress((void**)&buf2, g_buf2);
    cudaGetSymbolAddress((void**)&msgc, g_msgc);
    cudaGetSymbolAddress((void**)&zc, g_zc);
    cudaGetSymbolAddress((void**)&msgl, g_msgl);
    cudaGetSymbolAddress((void**)&zl, g_zl);
    cudaGetSymbolAddress((void**)&v1, g_v1);
    cudaGetSymbolAddress((void**)&v2, g_v2);
    cudaGetSymbolAddress((void**)&logitsA, g_logitsA);
    cudaGetSymbolAddress((void**)&wp, g_wpool);
    g_wp_host = wp;

    cudaFuncSetAttribute(tgemm_kernel, cudaFuncAttributeMaxDynamicSharedMemorySize,
                         TG_SMEM);

    // weight pool offsets ([N,K] transposed, element offsets)
    const int oLC0 = 0, oLC1 = 65536, oLC2 = 131072;
    const int oCL0 = 196608, oCL1 = 262144, oCL2 = 327680;
    const int oCWx = 393216, oCWh = 655360;
    const int oLWxa = 917504, oLWxb = 1179648, oLWh = 1441792;
    const int oVW0a = 1703936, oVW0b = 1835008, oVW1 = 1966080;

    struct { const float* src; int K, N, off; } WS[14] = {
        {LC_W0, 256, 256, oLC0}, {LC_W1, 256, 256, oLC1}, {LC_W2, 256, 256, oLC2},
        {CL_W0, 256, 256, oCL0}, {CL_W1, 256, 256, oCL1}, {CL_W2, 256, 256, oCL2},
        {C_Wx, 256, 1024, oCWx}, {C_Wh, 256, 1024, oCWh},
        {L_Wx, 256, 1024, oLWxa}, {L_Wx + 256 * 1024, 256, 1024, oLWxb},
        {L_Wh, 256, 1024, oLWh},
        {V_W0, 256, 512, oVW0a}, {V_W0 + 256 * 512, 256, 512, oVW0b},
        {V_W1, 512, 512, oVW1},
    };
    for (int i = 0; i < 14; i++) {
        int n = WS[i].K * WS[i].N;
        wsplit_kernel<<<(n + 255) / 256, 256>>>(WS[i].src, WS[i].K, WS[i].N,
                                                WS[i].off);
    }

    // preprocessing
    edge_prep_kernel<<<(NE + 255) / 256, 256>>>(clause_lits);
    zero_cnt_kernel<<<(NL + 255) / 256, 256>>>();
    count_kernel<<<(NE + 255) / 256, 256>>>();
    scan_kernel<<<1, 1024>>>();
    zero_cnt_kernel<<<(NL + 255) / 256, 256>>>();
    fill_kernel<<<(NE + 255) / 256, 256>>>();
    sort_kernel<<<(NL + 127) / 128, 128>>>();
    init_state_kernel<<<(NC * FM + 255) / 256, 256>>>(L_init, C_init);

    // ---- 32 message-passing rounds (vote/loss deferred, batched after) ----
    for (int r = 0; r < ROUNDS; r++) {
        const float* lhr = lha + (size_t)r * NL * FM;        // slot r
        float* lhw = lha + (size_t)(r + 1) * NL * FM;        // slot r+1

        // literal -> clause MLP
        launch_tg(lhr, 256, oLC0, nullptr, 0, 0, nullptr, 0, 0,
                  LC_b0, buf1, NL, 256, GF_RELU);
        launch_tg(buf1, 256, oLC1, nullptr, 0, 0, nullptr, 0, 0,
                  LC_b1, buf2, NL, 256, GF_RELU);
        launch_tg(buf2, 256, oLC2, nullptr, 0, 0, nullptr, 0, 0,
                  LC_b2, buf1, NL, 256, 0);
        clause_gather_kernel<<<NC, FM>>>(buf1, msgc);

        // clause LSTM (fused x/h GEMM, K=512; ch/cc in place)
        launch_tg(msgc, 256, oCWx, ch, 256, oCWh, nullptr, 0, 0,
                  C_b, zc, NC, 1024, 0);
        lstm_kernel<<<(NC * FM + 255) / 256, 256>>>(zc, ch, cc, NC);

        // clause -> literal MLP
        launch_tg(ch, 256, oCL0, nullptr, 0, 0, nullptr, 0, 0,
                  CL_b0, buf1, NC, 256, GF_RELU);
        launch_tg(buf1, 256, oCL1, nullptr, 0, 0, nullptr, 0, 0,
                  CL_b1, buf2, NC, 256, GF_RELU);
        launch_tg(buf2, 256, oCL2, nullptr, 0, 0, nullptr, 0, 0,
                  CL_b2, buf1, NC, 256, 0);
        lit_gather_kernel<<<NL, FM>>>(buf1, msgl);

        // literal LSTM: z = [msgl, flipped(lh_r), lh_r]; h -> slot r+1
        launch_tg(msgl, 256, oLWxa, lhr, 256, oLWxb, lhr, 256, oLWh,
                  L_b, zl, NL, 1024, GF_FLIP2);
        lstm_kernel<<<(NL * FM + 255) / 256, 256>>>(zl, lhw, lc, NL);
    }

    // ---- batched vote + loss: 4 chunks of 8 rounds (slots 1..32) ----
    for (int t = 0; t < ROUNDS / VCH; t++) {
        const float* sb = lha + (size_t)(1 + VCH * t) * NL * FM;
        launch_tg(sb, 256, oVW0a, sb + (size_t)NV * FM, 256, oVW0b,
                  nullptr, 0, 0, V_b0, v1, VM, 512, GF_RELU | GF_VOTEMAP);
        launch_tg(v1, 512, oVW1, nullptr, 0, 0, nullptr, 0, 0,
                  V_b1, v2, VM, 512, GF_RELU);
        vote_out_kernel<<<VM, 128>>>(v2, V_W2, V_b2, logitsA + (size_t)t * VM);
        loss_kernel<<<(VCH * NC + 255) / 256, 256>>>(logitsA + (size_t)t * VM);
    }

    finalize_kernel<<<(NV + 255) / 256, 256>>>((float*)d_out, out_size);
}

// round 13
// speedup vs baseline: 1.2886x; 1.2169x over previous
#include <cuda_runtime.h>
#include <cuda_bf16.h>
#include <math.h>
#include <stdint.h>

#define NV 4000
#define NL 8000          // 2*NV literals
#define NC 16800
#define NE 50400         // NC*3 edges
#define FM 256
#define ROUNDS 32

// ---------------------------------------------------------------------------
// PTX helpers (baseline ISA only: ldmatrix + mma.sync + cp.async, sm_80+)
// ---------------------------------------------------------------------------
__device__ __forceinline__ uint32_t smem_u32(const void* p) {
    uint32_t a;
    asm("{ .reg .u64 t; cvta.to.shared.u64 t, %1; cvt.u32.u64 %0, t; }"
        : "=r"(a) : "l"(p));
    return a;
}
__device__ __forceinline__ void ldsm_x4(uint32_t& r0, uint32_t& r1,
                                        uint32_t& r2, uint32_t& r3, uint32_t a) {
    asm volatile("ldmatrix.sync.aligned.m8n8.x4.shared.b16 {%0,%1,%2,%3}, [%4];"
                 : "=r"(r0), "=r"(r1), "=r"(r2), "=r"(r3) : "r"(a));
}
__device__ __forceinline__ void ldsm_x2(uint32_t& r0, uint32_t& r1, uint32_t a) {
    asm volatile("ldmatrix.sync.aligned.m8n8.x2.shared.b16 {%0,%1}, [%2];"
                 : "=r"(r0), "=r"(r1) : "r"(a));
}
__device__ __forceinline__ void mma_bf16(float* c, const uint32_t* a,
                                         const uint32_t* b) {
    asm volatile(
        "mma.sync.aligned.m16n8k16.row.col.f32.bf16.bf16.f32 "
        "{%0,%1,%2,%3}, {%4,%5,%6,%7}, {%8,%9}, {%0,%1,%2,%3};"
        : "+f"(c[0]), "+f"(c[1]), "+f"(c[2]), "+f"(c[3])
        : "r"(a[0]), "r"(a[1]), "r"(a[2]), "r"(a[3]), "r"(b[0]), "r"(b[1]));
}
__device__ __forceinline__ void cpasync16(uint32_t saddr, const void* g) {
    asm volatile("cp.async.cg.shared.global [%0], [%1], 16;"
                 :: "r"(saddr), "l"(g) : "memory");
}
#define CPASYNC_COMMIT() asm volatile("cp.async.commit_group;" ::: "memory")
#define CPASYNC_WAIT0()  asm volatile("cp.async.wait_group 0;" ::: "memory")

#define SWZ128(off) ((off) ^ (((off) >> 3) & 0x70))

// ---------------------------------------------------------------------------
// Scratch (static device globals)
// ---------------------------------------------------------------------------
__device__ float g_lh[NL * FM];
__device__ float g_lc[NL * FM];
__device__ float g_ch[NC * FM];
__device__ float g_cc[NC * FM];
__device__ float g_buf1[NC * FM];
__device__ float g_buf2[NC * FM];
__device__ float g_msgc[NC * FM];
__device__ float g_zc[NC * 4 * FM];
__device__ float g_msgl[NL * FM];
__device__ float g_zl[NL * 4 * FM];
__device__ float g_v1[NV * 2 * FM];
__device__ float g_v2[NV * 2 * FM];
__device__ float g_logits[NV];
__device__ float g_loss;

__device__ int g_lit[NE];
__device__ int g_cnt[NL];
__device__ int g_off[NL + 1];
__device__ int g_ledges[NE];

// weight pool: transposed [N,K] bf16, hi then lo halves
#define WTOT 2228224
__device__ __nv_bfloat16 g_wpool[2 * WTOT];

// ---------------------------------------------------------------------------
// Edge preprocessing (unchanged, known-correct)
// ---------------------------------------------------------------------------
__global__ void edge_prep_kernel(const int* __restrict__ lits) {
    int e = blockIdx.x * blockDim.x + threadIdx.x;
    if (e >= NE) return;
    int v = lits[e];
    int va = (v > 0 ? v : -v) - 1;
    g_lit[e] = (v > 0) ? va : (NV + va);
}
__global__ void zero_cnt_kernel() {
    int i = blockIdx.x * blockDim.x + threadIdx.x;
    if (i < NL) g_cnt[i] = 0;
}
__global__ void count_kernel() {
    int e = blockIdx.x * blockDim.x + threadIdx.x;
    if (e < NE) atomicAdd(&g_cnt[g_lit[e]], 1);
}
__global__ void scan_kernel() {
    __shared__ int part[1024];
    const int t = threadIdx.x;
    const int CH = 8;
    int base = t * CH;
    int local[CH];
    int s = 0;
    #pragma unroll
    for (int i = 0; i < CH; i++) {
        int idx = base + i;
        int v = (idx < NL) ? g_cnt[idx] : 0;
        local[i] = s;
        s += v;
    }
    part[t] = s;
    __syncthreads();
    for (int d = 1; d < 1024; d <<= 1) {
        int v = (t >= d) ? part[t - d] : 0;
        __syncthreads();
        part[t] += v;
        __syncthreads();
    }
    int off = (t == 0) ? 0 : part[t - 1];
    #pragma unroll
    for (int i = 0; i < CH; i++) {
        int idx = base + i;
        if (idx < NL) g_off[idx] = off + local[i];
    }
    if (t == 1023) g_off[NL] = part[1023];
}
__global__ void fill_kernel() {
    int e = blockIdx.x * blockDim.x + threadIdx.x;
    if (e >= NE) return;
    int l = g_lit[e];
    int pos = atomicAdd(&g_cnt[l], 1);
    g_ledges[g_off[l] + pos] = e;
}
__global__ void sort_kernel() {
    int l = blockIdx.x * blockDim.x + threadIdx.x;
    if (l >= NL) return;
    int beg = g_off[l], end = g_off[l + 1];
    for (int i = beg + 1; i < end; i++) {
        int key = g_ledges[i];
        int j = i - 1;
        while (j >= beg && g_ledges[j] > key) {
            g_ledges[j + 1] = g_ledges[j];
            j--;
        }
        g_ledges[j + 1] = key;
    }
}
__global__ void init_state_kernel(const float* __restrict__ Li,
                                  const float* __restrict__ Ci) {
    int idx = blockIdx.x * blockDim.x + threadIdx.x;
    const float inv = 0.0625f;
    if (idx < NL * FM) {
        g_lh[idx] = Li[idx & (FM - 1)] * inv;
        g_lc[idx] = 0.f;
    }
    if (idx < NC * FM) {
        g_ch[idx] = Ci[idx & (FM - 1)] * inv;
        g_cc[idx] = 0.f;
    }
    if (idx == 0) g_loss = 0.f;
}

// ---------------------------------------------------------------------------
// Weight split+transpose: src fp32 [K,N] -> pool hi/lo bf16 [N,K]
// ---------------------------------------------------------------------------
__global__ void wsplit_kernel(const float* __restrict__ src, int K, int N, int off) {
    int idx = blockIdx.x * blockDim.x + threadIdx.x;
    if (idx >= K * N) return;
    int k = idx / N, n = idx - k * N;
    float v = src[idx];
    __nv_bfloat16 h = __float2bfloat16_rn(v);
    __nv_bfloat16 l = __float2bfloat16_rn(v - __bfloat162float(h));
    g_wpool[off + (size_t)n * K + k] = h;
    g_wpool[WTOT + off + (size_t)n * K + k] = l;
}

// ---------------------------------------------------------------------------
// Tensor-core GEMM (mma.sync bf16, fp32 accum, Markidis 3-term split):
//   C[M,N] = concat_K(A1,A2,A3) @ concat_rows(W1,W2,W3) (+bias)(relu)
// Single-buffered 64KB tiles, __launch_bounds__(256,2) -> 2 CTAs/SM.
// Cross-CTA overlap hides staging latency / barrier drains.
// GF_FLIP2: segment-2 rows are read flip-permuted (l<NV -> l+NV else l-NV).
// ---------------------------------------------------------------------------
#define GF_RELU 1
#define GF_FLIP2 4
#define TG_SMEM 65536

__global__ __launch_bounds__(256, 2)
void tgemm_kernel(const float* __restrict__ A1, int K1,
                  const __nv_bfloat16* __restrict__ B1h,
                  const __nv_bfloat16* __restrict__ B1l,
                  const float* __restrict__ A2, int K2,
                  const __nv_bfloat16* __restrict__ B2h,
                  const __nv_bfloat16* __restrict__ B2l,
                  const float* __restrict__ A3, int K3,
                  const __nv_bfloat16* __restrict__ B3h,
                  const __nv_bfloat16* __restrict__ B3l,
                  const float* __restrict__ bias, float* __restrict__ C,
                  int M, int N, int flags) {
    extern __shared__ char smem[];
    char* tAh = smem;
    char* tAl = smem + 16384;
    const uint32_t sb0 = smem_u32(smem);
    const uint32_t sAh = sb0, sAl = sb0 + 16384;
    const uint32_t sBh = sb0 + 32768, sBl = sb0 + 49152;

    const int tid = threadIdx.x;
    const int wid = tid >> 5, lid = tid & 31;
    const int bm = blockIdx.y * 128;
    const int bn = blockIdx.x * 128;
    const int wm = (wid & 1) * 64;
    const int wn = (wid >> 1) * 32;

    float acc[4][4][4];
    #pragma unroll
    for (int i = 0; i < 4; i++)
        #pragma unroll
        for (int j = 0; j < 4; j++)
            #pragma unroll
            for (int q = 0; q < 4; q++) acc[i][j][q] = 0.f;

    const int nch = (K1 + K2 + K3) >> 6;

    for (int c = 0; c < nch; c++) {
        int kk0 = c << 6;
        const float* A = A1;
        const __nv_bfloat16 *bh = B1h, *bl = B1l;
        int ldk = K1, kk = kk0, flip = 0;
        if (kk0 >= K1 + K2) { A = A3; bh = B3h; bl = B3l; ldk = K3; kk = kk0 - K1 - K2; }
        else if (kk0 >= K1) { A = A2; bh = B2h; bl = B2l; ldk = K2;
                              kk = kk0 - K1; flip = (flags & GF_FLIP2); }

        __syncthreads();   // protect tiles from previous iteration's readers

        // ---- B prefetch via cp.async (pre-split bf16 [N,K], swizzled) ----
        #pragma unroll
        for (int i = 0; i < 8; i++) {
            int idx = i * 256 + tid;           // 0..2047
            int half = idx >> 10;              // 0: hi, 1: lo
            int j = idx & 1023;
            int row = j >> 3;                  // n local 0..127
            int c16 = (j & 7) << 4;            // byte offset 0..112
            const __nv_bfloat16* src =
                (half ? bl : bh) + (size_t)(bn + row) * ldk + kk + (c16 >> 1);
            cpasync16((half ? sBl : sBh) + SWZ128((uint32_t)(row * 128 + c16)),
                      src);
        }
        CPASYNC_COMMIT();

        // ---- stage A (fp32 -> split bf16 hi/lo, SW128), overlaps with B ----
        #pragma unroll
        for (int i = 0; i < 8; i++) {
            int idx = i * 256 + tid;           // 0..2047
            int row = idx >> 4;
            int c4 = (idx & 15) << 2;          // k offset 0..60
            int gr = bm + row;
            float4 v = make_float4(0.f, 0.f, 0.f, 0.f);
            if (gr < M) {
                int ar = flip ? (gr < NV ? gr + NV : gr - NV) : gr;
                v = *(const float4*)&A[(size_t)ar * ldk + kk + c4];
            }
            __nv_bfloat16 h0 = __float2bfloat16_rn(v.x);
            __nv_bfloat16 h1 = __float2bfloat16_rn(v.y);
            __nv_bfloat16 h2 = __float2bfloat16_rn(v.z);
            __nv_bfloat16 h3 = __float2bfloat16_rn(v.w);
            __nv_bfloat162 hp0 = __halves2bfloat162(h0, h1);
            __nv_bfloat162 hp1 = __halves2bfloat162(h2, h3);
            __nv_bfloat162 lp0 = __halves2bfloat162(
                __float2bfloat16_rn(v.x - __bfloat162float(h0)),
                __float2bfloat16_rn(v.y - __bfloat162float(h1)));
            __nv_bfloat162 lp1 = __halves2bfloat162(
                __float2bfloat16_rn(v.z - __bfloat162float(h2)),
                __float2bfloat16_rn(v.w - __bfloat162float(h3)));
            uint32_t off = SWZ128((uint32_t)(row * 128 + c4 * 2));
            *(uint2*)(tAh + off) = make_uint2(*(uint32_t*)&hp0, *(uint32_t*)&hp1);
            *(uint2*)(tAl + off) = make_uint2(*(uint32_t*)&lp0, *(uint32_t*)&lp1);
        }

        CPASYNC_WAIT0();
        __syncthreads();

        // ---- compute: 4 k16 steps ----
        #pragma unroll
        for (int s = 0; s < 4; s++) {
            int kb = s * 32;
            uint32_t ah[4][4], al[4][4], bhf[4][2], blf[4][2];
            int arow = (lid & 15);
            int acolb = kb + (lid >> 4) * 16;
            #pragma unroll
            for (int mt = 0; mt < 4; mt++) {
                uint32_t o = SWZ128((uint32_t)((wm + mt * 16 + arow) * 128 + acolb));
                ldsm_x4(ah[mt][0], ah[mt][1], ah[mt][2], ah[mt][3], sAh + o);
                ldsm_x4(al[mt][0], al[mt][1], al[mt][2], al[mt][3], sAl + o);
            }
            int brow = (lid & 7);
            int bcolb = kb + ((lid >> 3) & 1) * 16;
            #pragma unroll
            for (int nt = 0; nt < 4; nt++) {
                uint32_t o = SWZ128((uint32_t)((wn + nt * 8 + brow) * 128 + bcolb));
                ldsm_x2(bhf[nt][0], bhf[nt][1], sBh + o);
                ldsm_x2(blf[nt][0], blf[nt][1], sBl + o);
            }
            #pragma unroll
            for (int mt = 0; mt < 4; mt++)
                #pragma unroll
                for (int nt = 0; nt < 4; nt++) {
                    mma_bf16(acc[mt][nt], ah[mt], bhf[nt]);
                    mma_bf16(acc[mt][nt], al[mt], bhf[nt]);
                    mma_bf16(acc[mt][nt], ah[mt], blf[nt]);
                }
        }
    }

    // ---- epilogue: direct float2 stores with bias/relu ----
    #pragma unroll
    for (int mt = 0; mt < 4; mt++) {
        int r0 = bm + wm + mt * 16 + (lid >> 2);
        #pragma unroll
        for (int nt = 0; nt < 4; nt++) {
            int col = bn + wn + nt * 8 + (lid & 3) * 2;
            float bx = 0.f, by = 0.f;
            if (bias) { bx = bias[col]; by = bias[col + 1]; }
            float2 v0 = make_float2(acc[mt][nt][0] + bx, acc[mt][nt][1] + by);
            float2 v1 = make_float2(acc[mt][nt][2] + bx, acc[mt][nt][3] + by);
            if (flags & GF_RELU) {
                v0.x = fmaxf(v0.x, 0.f); v0.y = fmaxf(v0.y, 0.f);
                v1.x = fmaxf(v1.x, 0.f); v1.y = fmaxf(v1.y, 0.f);
            }
            if (r0 < M)     *(float2*)&C[(size_t)r0 * N + col] = v0;
            if (r0 + 8 < M) *(float2*)&C[(size_t)(r0 + 8) * N + col] = v1;
        }
    }
}

// ---------------------------------------------------------------------------
// Elementwise / gather kernels
// ---------------------------------------------------------------------------
__device__ __forceinline__ float sigm(float x) { return 1.f / (1.f + expf(-x)); }

__global__ void lstm_kernel(const float* __restrict__ z,
                            float* __restrict__ h, float* __restrict__ c, int R) {
    int idx = blockIdx.x * blockDim.x + threadIdx.x;
    if (idx >= R * FM) return;
    int r = idx / FM, f = idx - r * FM;
    const float* zr = z + (size_t)r * 4 * FM;
    float zi = zr[f], zf = zr[FM + f], zg = zr[2 * FM + f], zo = zr[3 * FM + f];
    float cv = sigm(zf) * c[idx] + sigm(zi) * tanhf(zg);
    c[idx] = cv;
    h[idx] = sigm(zo) * tanhf(cv);
}

__global__ void clause_gather_kernel(const float* __restrict__ pre,
                                     float* __restrict__ out) {
    int c = blockIdx.x;
    int f = threadIdx.x;
    int e0 = c * 3;
    float s = pre[(size_t)g_lit[e0] * FM + f] +
              pre[(size_t)g_lit[e0 + 1] * FM + f] +
              pre[(size_t)g_lit[e0 + 2] * FM + f];
    out[(size_t)c * FM + f] = s;
}

__global__ void lit_gather_kernel(const float* __restrict__ cl_pre,
                                  float* __restrict__ msgl) {
    int l = blockIdx.x;
    int f = threadIdx.x;
    int beg = g_off[l], end = g_off[l + 1];
    float s = 0.f;
    for (int i = beg; i < end; i++) {
        int e = g_ledges[i];
        s += cl_pre[(size_t)(e / 3) * FM + f];
    }
    msgl[(size_t)l * FM + f] = s;
}

__global__ void vote_out_kernel(const float* __restrict__ H,
                                const float* __restrict__ W,
                                const float* __restrict__ b) {
    int r = blockIdx.x;
    float s = 0.f;
    for (int k = threadIdx.x; k < 2 * FM; k += blockDim.x)
        s += H[(size_t)r * 2 * FM + k] * W[k];
    for (int o = 16; o; o >>= 1) s += __shfl_down_sync(0xffffffffu, s, o);
    __shared__ float sm[4];
    if ((threadIdx.x & 31) == 0) sm[threadIdx.x >> 5] = s;
    __syncthreads();
    if (threadIdx.x == 0)
        g_logits[r] = sm[0] + sm[1] + sm[2] + sm[3] + b[0];
}

__device__ __forceinline__ float softplus_f(float x) {
    return x > 0.f ? x + log1pf(expf(-x)) : log1pf(expf(x));
}

__global__ void loss_kernel() {
    int c = blockIdx.x * blockDim.x + threadIdx.x;
    float t = 0.f;
    if (c < NC) {
        float s = 0.f;
        #pragma unroll
        for (int k = 0; k < 3; k++) {
            int lit = g_lit[c * 3 + k];
            float sign = (lit < NV) ? 1.f : -1.f;
            int var = (lit < NV) ? lit : lit - NV;
            s += softplus_f(g_logits[var] * sign);
        }
        float cv = expf(-s);
        float l = -logf(1.f - cv + 1e-8f);
        t = l * l;
    }
    for (int o = 16; o; o >>= 1) t += __shfl_down_sync(0xffffffffu, t, o);
    __shared__ float sm[8];
    if ((threadIdx.x & 31) == 0) sm[threadIdx.x >> 5] = t;
    __syncthreads();
    if (threadIdx.x < 8) {
        float v = sm[threadIdx.x];
        for (int o = 4; o; o >>= 1) v += __shfl_down_sync(0xffu, v, o);
        if (threadIdx.x == 0) atomicAdd(&g_loss, v);
    }
}

__global__ void finalize_kernel(float* __restrict__ out, int out_size) {
    int i = blockIdx.x * blockDim.x + threadIdx.x;
    if (i < NV && i < out_size) out[i] = g_logits[i];
    if (i == 0 && out_size > NV) out[NV] = g_loss / (float)ROUNDS;
}

// ---------------------------------------------------------------------------
// Host orchestration (identical to R8 best-known)
// ---------------------------------------------------------------------------
static const __nv_bfloat16* g_wp_host;

static inline void launch_tg(const float* A1, int K1, int off1,
                             const float* A2, int K2, int off2,
                             const float* A3, int K3, int off3,
                             const float* bias, float* C, int M, int N, int flags) {
    const __nv_bfloat16* wp = g_wp_host;
    dim3 grid(N / 128, (M + 127) / 128);
    tgemm_kernel<<<grid, 256, TG_SMEM>>>(
        A1, K1, wp + off1, wp + WTOT + off1,
        A2, K2, A2 ? wp + off2 : nullptr, A2 ? wp + WTOT + off2 : nullptr,
        A3, K3, A3 ? wp + off3 : nullptr, A3 ? wp + WTOT + off3 : nullptr,
        bias, C, M, N, flags);
}

extern "C" void kernel_launch(void* const* d_in, const int* in_sizes, int n_in,
                              void* d_out, int out_size) {
    int base = (n_in >= 2 && in_sizes[1] == 1) ? 1 : 0;
    const int* clause_lits = (const int*)d_in[0];
    const float* P[26];
    for (int i = 0; i < 26; i++) P[i] = (const float*)d_in[1 + base + i];
    const float *L_init = P[0], *C_init = P[1];
    const float *LC_W0 = P[2], *LC_b0 = P[3], *LC_W1 = P[4], *LC_b1 = P[5],
                *LC_W2 = P[6], *LC_b2 = P[7];
    const float *CL_W0 = P[8], *CL_b0 = P[9], *CL_W1 = P[10], *CL_b1 = P[11],
                *CL_W2 = P[12], *CL_b2 = P[13];
    const float *C_Wx = P[14], *C_Wh = P[15], *C_b = P[16];
    const float *L_Wx = P[17], *L_Wh = P[18], *L_b = P[19];
    const float *V_W0 = P[20], *V_b0 = P[21], *V_W1 = P[22], *V_b1 = P[23],
                *V_W2 = P[24], *V_b2 = P[25];

    float *lh, *lc, *ch, *cc, *buf1, *buf2, *msgc, *zc, *msgl, *zl, *v1, *v2;
    __nv_bfloat16* wp;
    cudaGetSymbolAddress((void**)&lh, g_lh);
    cudaGetSymbolAddress((void**)&lc, g_lc);
    cudaGetSymbolAddress((void**)&ch, g_ch);
    cudaGetSymbolAddress((void**)&cc, g_cc);
    cudaGetSymbolAddress((void**)&buf1, g_buf1);
    cudaGetSymbolAddress((void**)&buf2, g_buf2);
    cudaGetSymbolAddress((void**)&msgc, g_msgc);
    cudaGetSymbolAddress((void**)&zc, g_zc);
    cudaGetSymbolAddress((void**)&msgl, g_msgl);
    cudaGetSymbolAddress((void**)&zl, g_zl);
    cudaGetSymbolAddress((void**)&v1, g_v1);
    cudaGetSymbolAddress((void**)&v2, g_v2);
    cudaGetSymbolAddress((void**)&wp, g_wpool);
    g_wp_host = wp;

    cudaFuncSetAttribute(tgemm_kernel, cudaFuncAttributeMaxDynamicSharedMemorySize,
                         TG_SMEM);

    // weight pool offsets ([N,K] transposed, element offsets)
    const int oLC0 = 0, oLC1 = 65536, oLC2 = 131072;
    const int oCL0 = 196608, oCL1 = 262144, oCL2 = 327680;
    const int oCWx = 393216, oCWh = 655360;
    const int oLWxa = 917504, oLWxb = 1179648, oLWh = 1441792;
    const int oVW0a = 1703936, oVW0b = 1835008, oVW1 = 1966080;

    struct { const float* src; int K, N, off; } WS[14] = {
        {LC_W0, 256, 256, oLC0}, {LC_W1, 256, 256, oLC1}, {LC_W2, 256, 256, oLC2},
        {CL_W0, 256, 256, oCL0}, {CL_W1, 256, 256, oCL1}, {CL_W2, 256, 256, oCL2},
        {C_Wx, 256, 1024, oCWx}, {C_Wh, 256, 1024, oCWh},
        {L_Wx, 256, 1024, oLWxa}, {L_Wx + 256 * 1024, 256, 1024, oLWxb},
        {L_Wh, 256, 1024, oLWh},
        {V_W0, 256, 512, oVW0a}, {V_W0 + 256 * 512, 256, 512, oVW0b},
        {V_W1, 512, 512, oVW1},
    };
    for (int i = 0; i < 14; i++) {
        int n = WS[i].K * WS[i].N;
        wsplit_kernel<<<(n + 255) / 256, 256>>>(WS[i].src, WS[i].K, WS[i].N,
                                                WS[i].off);
    }

    // preprocessing
    edge_prep_kernel<<<(NE + 255) / 256, 256>>>(clause_lits);
    zero_cnt_kernel<<<(NL + 255) / 256, 256>>>();
    count_kernel<<<(NE + 255) / 256, 256>>>();
    scan_kernel<<<1, 1024>>>();
    zero_cnt_kernel<<<(NL + 255) / 256, 256>>>();
    fill_kernel<<<(NE + 255) / 256, 256>>>();
    sort_kernel<<<(NL + 127) / 128, 128>>>();
    init_state_kernel<<<(NC * FM + 255) / 256, 256>>>(L_init, C_init);

    for (int r = 0; r < ROUNDS; r++) {
        // literal -> clause MLP
        launch_tg(lh, 256, oLC0, nullptr, 0, 0, nullptr, 0, 0,
                  LC_b0, buf1, NL, 256, GF_RELU);
        launch_tg(buf1, 256, oLC1, nullptr, 0, 0, nullptr, 0, 0,
                  LC_b1, buf2, NL, 256, GF_RELU);
        launch_tg(buf2, 256, oLC2, nullptr, 0, 0, nullptr, 0, 0,
                  LC_b2, buf1, NL, 256, 0);
        clause_gather_kernel<<<NC, FM>>>(buf1, msgc);

        // clause LSTM (fused x/h GEMM, K=512)
        launch_tg(msgc, 256, oCWx, ch, 256, oCWh, nullptr, 0, 0,
                  C_b, zc, NC, 1024, 0);
        lstm_kernel<<<(NC * FM + 255) / 256, 256>>>(zc, ch, cc, NC);

        // clause -> literal MLP
        launch_tg(ch, 256, oCL0, nullptr, 0, 0, nullptr, 0, 0,
                  CL_b0, buf1, NC, 256, GF_RELU);
        launch_tg(buf1, 256, oCL1, nullptr, 0, 0, nullptr, 0, 0,
                  CL_b1, buf2, NC, 256, GF_RELU);
        launch_tg(buf2, 256, oCL2, nullptr, 0, 0, nullptr, 0, 0,
                  CL_b2, buf1, NC, 256, 0);
        lit_gather_kernel<<<NL, FM>>>(buf1, msgl);

        // literal LSTM: z = [msgl, flipped(lh), lh] @ rows(LWxa, LWxb, LWh)
        launch_tg(msgl, 256, oLWxa, lh, 256, oLWxb, lh, 256, oLWh,
                  L_b, zl, NL, 1024, GF_FLIP2);
        lstm_kernel<<<(NL * FM + 255) / 256, 256>>>(zl, lh, lc, NL);

        // vote: x = [lh[:NV], lh[NV:]] along K (no concat materialization)
        launch_tg(lh, 256, oVW0a, lh + (size_t)NV * FM, 256, oVW0b, nullptr, 0, 0,
                  V_b0, v1, NV, 512, GF_RELU);
        launch_tg(v1, 512, oVW1, nullptr, 0, 0, nullptr, 0, 0,
                  V_b1, v2, NV, 512, GF_RELU);
        vote_out_kernel<<<NV, 128>>>(v2, V_W2, V_b2);
        loss_kernel<<<(NC + 255) / 256, 256>>>();
    }

    finalize_kernel<<<(NV + 255) / 256, 256>>>((float*)d_out, out_size);
}

// round 15
// speedup vs baseline: 1.3622x; 1.0571x over previous
#include <cuda_runtime.h>
#include <cuda_bf16.h>
#include <math.h>
#include <stdint.h>

#define NV 4000
#define NL 8000          // 2*NV literals
#define NC 16800
#define NE 50400         // NC*3 edges
#define FM 256
#define ROUNDS 32

// ---------------------------------------------------------------------------
// PTX helpers (baseline ISA only: ldmatrix + mma.sync + cp.async, sm_80+)
// ---------------------------------------------------------------------------
__device__ __forceinline__ uint32_t smem_u32(const void* p) {
    uint32_t a;
    asm("{ .reg .u64 t; cvta.to.shared.u64 t, %1; cvt.u32.u64 %0, t; }"
        : "=r"(a) : "l"(p));
    return a;
}
__device__ __forceinline__ void ldsm_x4(uint32_t& r0, uint32_t& r1,
                                        uint32_t& r2, uint32_t& r3, uint32_t a) {
    asm volatile("ldmatrix.sync.aligned.m8n8.x4.shared.b16 {%0,%1,%2,%3}, [%4];"
                 : "=r"(r0), "=r"(r1), "=r"(r2), "=r"(r3) : "r"(a));
}
__device__ __forceinline__ void ldsm_x2(uint32_t& r0, uint32_t& r1, uint32_t a) {
    asm volatile("ldmatrix.sync.aligned.m8n8.x2.shared.b16 {%0,%1}, [%2];"
                 : "=r"(r0), "=r"(r1) : "r"(a));
}
__device__ __forceinline__ void mma_bf16(float* c, const uint32_t* a,
                                         const uint32_t* b) {
    asm volatile(
        "mma.sync.aligned.m16n8k16.row.col.f32.bf16.bf16.f32 "
        "{%0,%1,%2,%3}, {%4,%5,%6,%7}, {%8,%9}, {%0,%1,%2,%3};"
        : "+f"(c[0]), "+f"(c[1]), "+f"(c[2]), "+f"(c[3])
        : "r"(a[0]), "r"(a[1]), "r"(a[2]), "r"(a[3]), "r"(b[0]), "r"(b[1]));
}
__device__ __forceinline__ void cpasync16(uint32_t saddr, const void* g) {
    asm volatile("cp.async.cg.shared.global [%0], [%1], 16;"
                 :: "r"(saddr), "l"(g) : "memory");
}
__device__ __forceinline__ void cpasync16z(uint32_t saddr, const void* g, int ssz) {
    asm volatile("cp.async.cg.shared.global [%0], [%1], 16, %2;"
                 :: "r"(saddr), "l"(g), "r"(ssz) : "memory");
}
#define CPASYNC_COMMIT() asm volatile("cp.async.commit_group;" ::: "memory")
#define CPASYNC_WAIT0()  asm volatile("cp.async.wait_group 0;" ::: "memory")

#define SWZ128(off) ((off) ^ (((off) >> 3) & 0x70))

// ---------------------------------------------------------------------------
// Scratch (static device globals)
// Activations are stored PRE-SPLIT as bf16 hi/lo pairs (hi array, then lo).
// ---------------------------------------------------------------------------
__device__ __nv_bfloat16 g_lhB[2 * NL * FM];
__device__ __nv_bfloat16 g_chB[2 * NC * FM];
__device__ __nv_bfloat16 g_b1B[2 * NC * FM];
__device__ __nv_bfloat16 g_b2B[2 * NC * FM];
__device__ __nv_bfloat16 g_msgcB[2 * NC * FM];
__device__ __nv_bfloat16 g_msglB[2 * NL * FM];
__device__ __nv_bfloat16 g_v1B[2 * NV * 2 * FM];
__device__ float g_pre[NC * FM];     // fp32 MLP output feeding gathers
__device__ float g_zc[NC * 4 * FM];
__device__ float g_zl[NL * 4 * FM];
__device__ float g_cc[NC * FM];
__device__ float g_lc[NL * FM];
__device__ float g_v2[NV * 2 * FM];
__device__ float g_logits[NV];
__device__ float g_loss;

__device__ int g_lit[NE];
__device__ int g_cnt[NL];
__device__ int g_off[NL + 1];
__device__ int g_ledges[NE];

// weight pool: transposed [N,K] bf16, hi then lo halves
#define WTOT 2228224
__device__ __nv_bfloat16 g_wpool[2 * WTOT];

__device__ __forceinline__ void split_write(__nv_bfloat16* hi, __nv_bfloat16* lo,
                                            size_t idx, float v) {
    __nv_bfloat16 h = __float2bfloat16_rn(v);
    hi[idx] = h;
    lo[idx] = __float2bfloat16_rn(v - __bfloat162float(h));
}

// ---------------------------------------------------------------------------
// Edge preprocessing (unchanged, known-correct)
// ---------------------------------------------------------------------------
__global__ void edge_prep_kernel(const int* __restrict__ lits) {
    int e = blockIdx.x * blockDim.x + threadIdx.x;
    if (e >= NE) return;
    int v = lits[e];
    int va = (v > 0 ? v : -v) - 1;
    g_lit[e] = (v > 0) ? va : (NV + va);
}
__global__ void zero_cnt_kernel() {
    int i = blockIdx.x * blockDim.x + threadIdx.x;
    if (i < NL) g_cnt[i] = 0;
}
__global__ void count_kernel() {
    int e = blockIdx.x * blockDim.x + threadIdx.x;
    if (e < NE) atomicAdd(&g_cnt[g_lit[e]], 1);
}
__global__ void scan_kernel() {
    __shared__ int part[1024];
    const int t = threadIdx.x;
    const int CH = 8;
    int base = t * CH;
    int local[CH];
    int s = 0;
    #pragma unroll
    for (int i = 0; i < CH; i++) {
        int idx = base + i;
        int v = (idx < NL) ? g_cnt[idx] : 0;
        local[i] = s;
        s += v;
    }
    part[t] = s;
    __syncthreads();
    for (int d = 1; d < 1024; d <<= 1) {
        int v = (t >= d) ? part[t - d] : 0;
        __syncthreads();
        part[t] += v;
        __syncthreads();
    }
    int off = (t == 0) ? 0 : part[t - 1];
    #pragma unroll
    for (int i = 0; i < CH; i++) {
        int idx = base + i;
        if (idx < NL) g_off[idx] = off + local[i];
    }
    if (t == 1023) g_off[NL] = part[1023];
}
__global__ void fill_kernel() {
    int e = blockIdx.x * blockDim.x + threadIdx.x;
    if (e >= NE) return;
    int l = g_lit[e];
    int pos = atomicAdd(&g_cnt[l], 1);
    g_ledges[g_off[l] + pos] = e;
}
__global__ void sort_kernel() {
    int l = blockIdx.x * blockDim.x + threadIdx.x;
    if (l >= NL) return;
    int beg = g_off[l], end = g_off[l + 1];
    for (int i = beg + 1; i < end; i++) {
        int key = g_ledges[i];
        int j = i - 1;
        while (j >= beg && g_ledges[j] > key) {
            g_ledges[j + 1] = g_ledges[j];
            j--;
        }
        g_ledges[j + 1] = key;
    }
}
__global__ void init_state_kernel(const float* __restrict__ Li,
                                  const float* __restrict__ Ci) {
    int idx = blockIdx.x * blockDim.x + threadIdx.x;
    const float inv = 0.0625f;
    if (idx < NL * FM) {
        split_write(g_lhB, g_lhB + NL * FM, idx, Li[idx & (FM - 1)] * inv);
        g_lc[idx] = 0.f;
    }
    if (idx < NC * FM) {
        split_write(g_chB, g_chB + NC * FM, idx, Ci[idx & (FM - 1)] * inv);
        g_cc[idx] = 0.f;
    }
    if (idx == 0) g_loss = 0.f;
}

// ---------------------------------------------------------------------------
// Weight split+transpose: src fp32 [K,N] -> pool hi/lo bf16 [N,K]
// ---------------------------------------------------------------------------
__global__ void wsplit_kernel(const float* __restrict__ src, int K, int N, int off) {
    int idx = blockIdx.x * blockDim.x + threadIdx.x;
    if (idx >= K * N) return;
    int k = idx / N, n = idx - k * N;
    float v = src[idx];
    __nv_bfloat16 h = __float2bfloat16_rn(v);
    __nv_bfloat16 l = __float2bfloat16_rn(v - __bfloat162float(h));
    g_wpool[off + (size_t)n * K + k] = h;
    g_wpool[WTOT + off + (size_t)n * K + k] = l;
}

// ---------------------------------------------------------------------------
// Tensor-core GEMM (mma.sync bf16, fp32 accum, Markidis 3-term split):
//   C[M,N] = concat_K(A1,A2,A3) @ concat_rows(W1,W2,W3) (+bias)(relu)
// A inputs are PRE-SPLIT bf16 hi/lo [M,K]; staging is pure cp.async.
// Single-buffered 64KB tiles, __launch_bounds__(256,2) -> 2 CTAs/SM.
// GF_FLIP2: segment-2 rows read flip-permuted (l<NV -> l+NV else l-NV).
// GF_SPLIT: output written as split bf16 hi/lo (Ch/Cl) instead of fp32 C.
// ---------------------------------------------------------------------------
#define GF_RELU 1
#define GF_FLIP2 4
#define GF_SPLIT 16
#define TG_SMEM 65536

__global__ __launch_bounds__(256, 2)
void tgemm_kernel(const __nv_bfloat16* __restrict__ A1h,
                  const __nv_bfloat16* __restrict__ A1l, int K1,
                  const __nv_bfloat16* __restrict__ B1h,
                  const __nv_bfloat16* __restrict__ B1l,
                  const __nv_bfloat16* __restrict__ A2h,
                  const __nv_bfloat16* __restrict__ A2l, int K2,
                  const __nv_bfloat16* __restrict__ B2h,
                  const __nv_bfloat16* __restrict__ B2l,
                  const __nv_bfloat16* __restrict__ A3h,
                  const __nv_bfloat16* __restrict__ A3l, int K3,
                  const __nv_bfloat16* __restrict__ B3h,
                  const __nv_bfloat16* __restrict__ B3l,
                  const float* __restrict__ bias, float* __restrict__ C,
                  __nv_bfloat16* __restrict__ Ch, __nv_bfloat16* __restrict__ Cl,
                  int M, int N, int flags) {
    extern __shared__ char smem[];
    const uint32_t sb0 = smem_u32(smem);
    const uint32_t sAh = sb0, sAl = sb0 + 16384;
    const uint32_t sBh = sb0 + 32768, sBl = sb0 + 49152;

    const int tid = threadIdx.x;
    const int wid = tid >> 5, lid = tid & 31;
    const int bm = blockIdx.y * 128;
    const int bn = blockIdx.x * 128;
    const int wm = (wid & 1) * 64;
    const int wn = (wid >> 1) * 32;

    float acc[4][4][4];
    #pragma unroll
    for (int i = 0; i < 4; i++)
        #pragma unroll
        for (int j = 0; j < 4; j++)
            #pragma unroll
            for (int q = 0; q < 4; q++) acc[i][j][q] = 0.f;

    const int nch = (K1 + K2 + K3) >> 6;

    for (int c = 0; c < nch; c++) {
        int kk0 = c << 6;
        const __nv_bfloat16 *ah = A1h, *al = A1l, *bh = B1h, *bl = B1l;
        int ldk = K1, kk = kk0, flip = 0;
        if (kk0 >= K1 + K2) {
            ah = A3h; al = A3l; bh = B3h; bl = B3l; ldk = K3; kk = kk0 - K1 - K2;
        } else if (kk0 >= K1) {
            ah = A2h; al = A2l; bh = B2h; bl = B2l; ldk = K2;
            kk = kk0 - K1; flip = (flags & GF_FLIP2);
        }

        __syncthreads();   // protect tiles from previous iteration's readers

        // ---- A stage: pure cp.async copy of pre-split bf16 (swizzled) ----
        #pragma unroll
        for (int i = 0; i < 8; i++) {
            int idx = i * 256 + tid;           // 0..2047
            int half = idx >> 10;              // 0: hi, 1: lo
            int j = idx & 1023;
            int row = j >> 3;                  // m local 0..127
            int c16 = (j & 7) << 4;            // byte offset 0..112
            int gr = bm + row;
            int inb = (gr < M);
            int ar = inb ? gr : 0;
            if (flip) ar = (ar < NV) ? ar + NV : ar - NV;
            const __nv_bfloat16* src =
                (half ? al : ah) + (size_t)ar * ldk + kk + (c16 >> 1);
            cpasync16z((half ? sAl : sAh) + SWZ128((uint32_t)(row * 128 + c16)),
                       src, inb ? 16 : 0);
        }

        // ---- B stage: cp.async copy (swizzled) ----
        #pragma unroll
        for (int i = 0; i < 8; i++) {
            int idx = i * 256 + tid;
            int half = idx >> 10;
            int j = idx & 1023;
            int row = j >> 3;                  // n local 0..127
            int c16 = (j & 7) << 4;
            const __nv_bfloat16* src =
                (half ? bl : bh) + (size_t)(bn + row) * ldk + kk + (c16 >> 1);
            cpasync16((half ? sBl : sBh) + SWZ128((uint32_t)(row * 128 + c16)),
                      src);
        }
        CPASYNC_COMMIT();
        CPASYNC_WAIT0();
        __syncthreads();

        // ---- compute: 4 k16 steps ----
        #pragma unroll
        for (int s = 0; s < 4; s++) {
            int kb = s * 32;
            uint32_t ahf[4][4], alf[4][4], bhf[4][2], blf[4][2];
            int arow = (lid & 15);
            int acolb = kb + (lid >> 4) * 16;
            #pragma unroll
            for (int mt = 0; mt < 4; mt++) {
                uint32_t o = SWZ128((uint32_t)((wm + mt * 16 + arow) * 128 + acolb));
                ldsm_x4(ahf[mt][0], ahf[mt][1], ahf[mt][2], ahf[mt][3], sAh + o);
                ldsm_x4(alf[mt][0], alf[mt][1], alf[mt][2], alf[mt][3], sAl + o);
            }
            int brow = (lid & 7);
            int bcolb = kb + ((lid >> 3) & 1) * 16;
            #pragma unroll
            for (int nt = 0; nt < 4; nt++) {
                uint32_t o = SWZ128((uint32_t)((wn + nt * 8 + brow) * 128 + bcolb));
                ldsm_x2(bhf[nt][0], bhf[nt][1], sBh + o);
                ldsm_x2(blf[nt][0], blf[nt][1], sBl + o);
            }
            #pragma unroll
            for (int mt = 0; mt < 4; mt++)
                #pragma unroll
                for (int nt = 0; nt < 4; nt++) {
                    mma_bf16(acc[mt][nt], ahf[mt], bhf[nt]);
                    mma_bf16(acc[mt][nt], alf[mt], bhf[nt]);
                    mma_bf16(acc[mt][nt], ahf[mt], blf[nt]);
                }
        }
    }

    // ---- epilogue ----
    #pragma unroll
    for (int mt = 0; mt < 4; mt++) {
        int r0 = bm + wm + mt * 16 + (lid >> 2);
        #pragma unroll
        for (int nt = 0; nt < 4; nt++) {
            int col = bn + wn + nt * 8 + (lid & 3) * 2;
            float bx = 0.f, by = 0.f;
            if (bias) { bx = bias[col]; by = bias[col + 1]; }
            float2 v0 = make_float2(acc[mt][nt][0] + bx, acc[mt][nt][1] + by);
            float2 v1 = make_float2(acc[mt][nt][2] + bx, acc[mt][nt][3] + by);
            if (flags & GF_RELU) {
                v0.x = fmaxf(v0.x, 0.f); v0.y = fmaxf(v0.y, 0.f);
                v1.x = fmaxf(v1.x, 0.f); v1.y = fmaxf(v1.y, 0.f);
            }
            if (flags & GF_SPLIT) {
                if (r0 < M) {
                    size_t ix = (size_t)r0 * N + col;
                    __nv_bfloat16 h0 = __float2bfloat16_rn(v0.x);
                    __nv_bfloat16 h1 = __float2bfloat16_rn(v0.y);
                    *(uint32_t*)&Ch[ix] = *(uint32_t*)&(
                        *(__nv_bfloat162*)&(__nv_bfloat162&)*(
                            __nv_bfloat162[]){__halves2bfloat162(h0, h1)});
                    __nv_bfloat162 lo = __halves2bfloat162(
                        __float2bfloat16_rn(v0.x - __bfloat162float(h0)),
                        __float2bfloat16_rn(v0.y - __bfloat162float(h1)));
                    *(uint32_t*)&Cl[ix] = *(uint32_t*)&lo;
                }
                if (r0 + 8 < M) {
                    size_t ix = (size_t)(r0 + 8) * N + col;
                    __nv_bfloat16 h0 = __float2bfloat16_rn(v1.x);
                    __nv_bfloat16 h1 = __float2bfloat16_rn(v1.y);
                    __nv_bfloat162 hi = __halves2bfloat162(h0, h1);
                    *(uint32_t*)&Ch[ix] = *(uint32_t*)&hi;
                    __nv_bfloat162 lo = __halves2bfloat162(
                        __float2bfloat16_rn(v1.x - __bfloat162float(h0)),
                        __float2bfloat16_rn(v1.y - __bfloat162float(h1)));
                    *(uint32_t*)&Cl[ix] = *(uint32_t*)&lo;
                }
            } else {
                if (r0 < M)     *(float2*)&C[(size_t)r0 * N + col] = v0;
                if (r0 + 8 < M) *(float2*)&C[(size_t)(r0 + 8) * N + col] = v1;
            }
        }
    }
}

// ---------------------------------------------------------------------------
// Elementwise / gather kernels
// ---------------------------------------------------------------------------
__device__ __forceinline__ float sigm(float x) { return 1.f / (1.f + expf(-x)); }

// LSTM elementwise: z fp32 (gate-blocked), c fp32 in/out, h written SPLIT bf16.
__global__ void lstm_kernel(const float* __restrict__ z,
                            __nv_bfloat16* __restrict__ hB, size_t loOff,
                            float* __restrict__ c, int R) {
    int idx = blockIdx.x * blockDim.x + threadIdx.x;
    if (idx >= R * FM) return;
    int r = idx / FM, f = idx - r * FM;
    const float* zr = z + (size_t)r * 4 * FM;
    float zi = zr[f], zf = zr[FM + f], zg = zr[2 * FM + f], zo = zr[3 * FM + f];
    float cv = sigm(zf) * c[idx] + sigm(zi) * tanhf(zg);
    c[idx] = cv;
    float hv = sigm(zo) * tanhf(cv);
    split_write(hB, hB + loOff, idx, hv);
}

__global__ void clause_gather_kernel(const float* __restrict__ pre,
                                     __nv_bfloat16* __restrict__ outB) {
    int c = blockIdx.x;
    int f = threadIdx.x;
    int e0 = c * 3;
    float s = pre[(size_t)g_lit[e0] * FM + f] +
              pre[(size_t)g_lit[e0 + 1] * FM + f] +
              pre[(size_t)g_lit[e0 + 2] * FM + f];
    split_write(outB, outB + (size_t)NC * FM, (size_t)c * FM + f, s);
}

__global__ void lit_gather_kernel(const float* __restrict__ cl_pre,
                                  __nv_bfloat16* __restrict__ outB) {
    int l = blockIdx.x;
    int f = threadIdx.x;
    int beg = g_off[l], end = g_off[l + 1];
    float s = 0.f;
    for (int i = beg; i < end; i++) {
        int e = g_ledges[i];
        s += cl_pre[(size_t)(e / 3) * FM + f];
    }
    split_write(outB, outB + (size_t)NL * FM, (size_t)l * FM + f, s);
}

__global__ void vote_out_kernel(const float* __restrict__ H,
                                const float* __restrict__ W,
                                const float* __restrict__ b) {
    int r = blockIdx.x;
    float s = 0.f;
    for (int k = threadIdx.x; k < 2 * FM; k += blockDim.x)
        s += H[(size_t)r * 2 * FM + k] * W[k];
    for (int o = 16; o; o >>= 1) s += __shfl_down_sync(0xffffffffu, s, o);
    __shared__ float sm[4];
    if ((threadIdx.x & 31) == 0) sm[threadIdx.x >> 5] = s;
    __syncthreads();
    if (threadIdx.x == 0)
        g_logits[r] = sm[0] + sm[1] + sm[2] + sm[3] + b[0];
}

__device__ __forceinline__ float softplus_f(float x) {
    return x > 0.f ? x + log1pf(expf(-x)) : log1pf(expf(x));
}

__global__ void loss_kernel() {
    int c = blockIdx.x * blockDim.x + threadIdx.x;
    float t = 0.f;
    if (c < NC) {
        float s = 0.f;
        #pragma unroll
        for (int k = 0; k < 3; k++) {
            int lit = g_lit[c * 3 + k];
            float sign = (lit < NV) ? 1.f : -1.f;
            int var = (lit < NV) ? lit : lit - NV;
            s += softplus_f(g_logits[var] * sign);
        }
        float cv = expf(-s);
        float l = -logf(1.f - cv + 1e-8f);
        t = l * l;
    }
    for (int o = 16; o; o >>= 1) t += __shfl_down_sync(0xffffffffu, t, o);
    __shared__ float sm[8];
    if ((threadIdx.x & 31) == 0) sm[threadIdx.x >> 5] = t;
    __syncthreads();
    if (threadIdx.x < 8) {
        float v = sm[threadIdx.x];
        for (int o = 4; o; o >>= 1) v += __shfl_down_sync(0xffu, v, o);
        if (threadIdx.x == 0) atomicAdd(&g_loss, v);
    }
}

__global__ void finalize_kernel(float* __restrict__ out, int out_size) {
    int i = blockIdx.x * blockDim.x + threadIdx.x;
    if (i < NV && i < out_size) out[i] = g_logits[i];
    if (i == 0 && out_size > NV) out[NV] = g_loss / (float)ROUNDS;
}

// ---------------------------------------------------------------------------
// Host orchestration
// ---------------------------------------------------------------------------
static const __nv_bfloat16* g_wp_host;

static inline void launch_tg(const __nv_bfloat16* A1, const __nv_bfloat16* A1l,
                             int K1, int off1,
                             const __nv_bfloat16* A2, const __nv_bfloat16* A2l,
                             int K2, int off2,
                             const __nv_bfloat16* A3, const __nv_bfloat16* A3l,
                             int K3, int off3,
                             const float* bias, float* C,
                             __nv_bfloat16* Ch, __nv_bfloat16* Cl,
                             int M, int N, int flags) {
    const __nv_bfloat16* wp = g_wp_host;
    dim3 grid(N / 128, (M + 127) / 128);
    tgemm_kernel<<<grid, 256, TG_SMEM>>>(
        A1, A1l, K1, wp + off1, wp + WTOT + off1,
        A2, A2l, K2, A2 ? wp + off2 : nullptr, A2 ? wp + WTOT + off2 : nullptr,
        A3, A3l, K3, A3 ? wp + off3 : nullptr, A3 ? wp + WTOT + off3 : nullptr,
        bias, C, Ch, Cl, M, N, flags);
}

extern "C" void kernel_launch(void* const* d_in, const int* in_sizes, int n_in,
                              void* d_out, int out_size) {
    int base = (n_in >= 2 && in_sizes[1] == 1) ? 1 : 0;
    const int* clause_lits = (const int*)d_in[0];
    const float* P[26];
    for (int i = 0; i < 26; i++) P[i] = (const float*)d_in[1 + base + i];
    const float *L_init = P[0], *C_init = P[1];
    const float *LC_W0 = P[2], *LC_b0 = P[3], *LC_W1 = P[4], *LC_b1 = P[5],
                *LC_W2 = P[6], *LC_b2 = P[7];
    const float *CL_W0 = P[8], *CL_b0 = P[9], *CL_W1 = P[10], *CL_b1 = P[11],
                *CL_W2 = P[12], *CL_b2 = P[13];
    const float *C_Wx = P[14], *C_Wh = P[15], *C_b = P[16];
    const float *L_Wx = P[17], *L_Wh = P[18], *L_b = P[19];
    const float *V_W0 = P[20], *V_b0 = P[21], *V_W1 = P[22], *V_b1 = P[23],
                *V_W2 = P[24], *V_b2 = P[25];

    __nv_bfloat16 *lhB, *chB, *b1B, *b2B, *msgcB, *msglB, *v1B, *wp;
    float *pre, *zc, *zl, *cc, *lc, *v2;
    cudaGetSymbolAddress((void**)&lhB, g_lhB);
    cudaGetSymbolAddress((void**)&chB, g_chB);
    cudaGetSymbolAddress((void**)&b1B, g_b1B);
    cudaGetSymbolAddress((void**)&b2B, g_b2B);
    cudaGetSymbolAddress((void**)&msgcB, g_msgcB);
    cudaGetSymbolAddress((void**)&msglB, g_msglB);
    cudaGetSymbolAddress((void**)&v1B, g_v1B);
    cudaGetSymbolAddress((void**)&pre, g_pre);
    cudaGetSymbolAddress((void**)&zc, g_zc);
    cudaGetSymbolAddress((void**)&zl, g_zl);
    cudaGetSymbolAddress((void**)&cc, g_cc);
    cudaGetSymbolAddress((void**)&lc, g_lc);
    cudaGetSymbolAddress((void**)&v2, g_v2);
    cudaGetSymbolAddress((void**)&wp, g_wpool);
    g_wp_host = wp;

    // lo-array base pointers
    __nv_bfloat16 *lhL = lhB + (size_t)NL * FM;
    __nv_bfloat16 *chL = chB + (size_t)NC * FM;
    __nv_bfloat16 *b1L = b1B + (size_t)NC * FM;
    __nv_bfloat16 *b2L = b2B + (size_t)NC * FM;
    __nv_bfloat16 *mcL = msgcB + (size_t)NC * FM;
    __nv_bfloat16 *mlL = msglB + (size_t)NL * FM;
    __nv_bfloat16 *v1L = v1B + (size_t)NV * 2 * FM;

    cudaFuncSetAttribute(tgemm_kernel, cudaFuncAttributeMaxDynamicSharedMemorySize,
                         TG_SMEM);

    // weight pool offsets ([N,K] transposed, element offsets)
    const int oLC0 = 0, oLC1 = 65536, oLC2 = 131072;
    const int oCL0 = 196608, oCL1 = 262144, oCL2 = 327680;
    const int oCWx = 393216, oCWh = 655360;
    const int oLWxa = 917504, oLWxb = 1179648, oLWh = 1441792;
    const int oVW0a = 1703936, oVW0b = 1835008, oVW1 = 1966080;

    struct { const float* src; int K, N, off; } WS[14] = {
        {LC_W0, 256, 256, oLC0}, {LC_W1, 256, 256, oLC1}, {LC_W2, 256, 256, oLC2},
        {CL_W0, 256, 256, oCL0}, {CL_W1, 256, 256, oCL1}, {CL_W2, 256, 256, oCL2},
        {C_Wx, 256, 1024, oCWx}, {C_Wh, 256, 1024, oCWh},
        {L_Wx, 256, 1024, oLWxa}, {L_Wx + 256 * 1024, 256, 1024, oLWxb},
        {L_Wh, 256, 1024, oLWh},
        {V_W0, 256, 512, oVW0a}, {V_W0 + 256 * 512, 256, 512, oVW0b},
        {V_W1, 512, 512, oVW1},
    };
    for (int i = 0; i < 14; i++) {
        int n = WS[i].K * WS[i].N;
        wsplit_kernel<<<(n + 255) / 256, 256>>>(WS[i].src, WS[i].K, WS[i].N,
                                                WS[i].off);
    }

    // preprocessing
    edge_prep_kernel<<<(NE + 255) / 256, 256>>>(clause_lits);
    zero_cnt_kernel<<<(NL + 255) / 256, 256>>>();
    count_kernel<<<(NE + 255) / 256, 256>>>();
    scan_kernel<<<1, 1024>>>();
    zero_cnt_kernel<<<(NL + 255) / 256, 256>>>();
    fill_kernel<<<(NE + 255) / 256, 256>>>();
    sort_kernel<<<(NL + 127) / 128, 128>>>();
    init_state_kernel<<<(NC * FM + 255) / 256, 256>>>(L_init, C_init);

    for (int r = 0; r < ROUNDS; r++) {
        // literal -> clause MLP (split bf16 intermediates)
        launch_tg(lhB, lhL, 256, oLC0, nullptr, nullptr, 0, 0,
                  nullptr, nullptr, 0, 0,
                  LC_b0, nullptr, b1B, b1L, NL, 256, GF_RELU | GF_SPLIT);
        launch_tg(b1B, b1L, 256, oLC1, nullptr, nullptr, 0, 0,
                  nullptr, nullptr, 0, 0,
                  LC_b1, nullptr, b2B, b2L, NL, 256, GF_RELU | GF_SPLIT);
        launch_tg(b2B, b2L, 256, oLC2, nullptr, nullptr, 0, 0,
                  nullptr, nullptr, 0, 0,
                  LC_b2, pre, nullptr, nullptr, NL, 256, 0);
        clause_gather_kernel<<<NC, FM>>>(pre, msgcB);

        // clause LSTM (fused x/h GEMM, K=512)
        launch_tg(msgcB, mcL, 256, oCWx, chB, chL, 256, oCWh,
                  nullptr, nullptr, 0, 0,
                  C_b, zc, nullptr, nullptr, NC, 1024, 0);
        lstm_kernel<<<(NC * FM + 255) / 256, 256>>>(zc, chB, (size_t)NC * FM,
                                                    cc, NC);

        // clause -> literal MLP
        launch_tg(chB, chL, 256, oCL0, nullptr, nullptr, 0, 0,
                  nullptr, nullptr, 0, 0,
                  CL_b0, nullptr, b1B, b1L, NC, 256, GF_RELU | GF_SPLIT);
        launch_tg(b1B, b1L, 256, oCL1, nullptr, nullptr, 0, 0,
                  nullptr, nullptr, 0, 0,
                  CL_b1, nullptr, b2B, b2L, NC, 256, GF_RELU | GF_SPLIT);
        launch_tg(b2B, b2L, 256, oCL2, nullptr, nullptr, 0, 0,
                  nullptr, nullptr, 0, 0,
                  CL_b2, pre, nullptr, nullptr, NC, 256, 0);
        lit_gather_kernel<<<NL, FM>>>(pre, msglB);

        // literal LSTM: z = [msgl, flipped(lh), lh] @ rows(LWxa, LWxb, LWh)
        launch_tg(msglB, mlL, 256, oLWxa, lhB, lhL, 256, oLWxb,
                  lhB, lhL, 256, oLWh,
                  L_b, zl, nullptr, nullptr, NL, 1024, GF_FLIP2);
        lstm_kernel<<<(NL * FM + 255) / 256, 256>>>(zl, lhB, (size_t)NL * FM,
                                                    lc, NL);

        // vote: x = [lh[:NV], lh[NV:]] along K
        launch_tg(lhB, lhL, 256, oVW0a,
                  lhB + (size_t)NV * FM, lhL + (size_t)NV * FM, 256, oVW0b,
                  nullptr, nullptr, 0, 0,
                  V_b0, nullptr, v1B, v1L, NV, 512, GF_RELU | GF_SPLIT);
        launch_tg(v1B, v1L, 512, oVW1, nullptr, nullptr, 0, 0,
                  nullptr, nullptr, 0, 0,
                  V_b1, v2, nullptr, nullptr, NV, 512, GF_RELU);
        vote_out_kernel<<<NV, 128>>>(v2, V_W2, V_b2);
        loss_kernel<<<(NC + 255) / 256, 256>>>();
    }

    finalize_kernel<<<(NV + 255) / 256, 256>>>((float*)d_out, out_size);
}